// round 2
// baseline (speedup 1.0000x reference)
#include <cuda_runtime.h>
#include <math.h>

#define BB 64
#define NN 4096
#define DD 128
#define SS 7
#define HH 256
#define NW 64                    // warp-partials per batch
#define ROWS_PER_WARP (NN / NW)  // 64
#define FLASH_WARPS 8
#define FLASH_BLOCKS_PER_B (NW / FLASH_WARPS)  // 8

// ---------------- device scratch (no allocations allowed) ----------------
__device__ __align__(16) float g_slots[BB * SS * DD];
__device__ __align__(16) float g_qt[BB * SS * DD];
__device__ __align__(16) float g_pm[BB * NW * SS];
__device__ __align__(16) float g_pl[BB * NW * SS];
__device__ __align__(16) float g_pacc[BB * NW * SS * DD];   // ~14.7 MB
__device__ __align__(16) float g_pes[BB * NW * DD];

// ---------------- slot init: slots = mu + sigma * noise ----------------
__global__ void k_init(const float* __restrict__ noise,
                       const float* __restrict__ mu,
                       const float* __restrict__ sg) {
    int i = blockIdx.x * blockDim.x + threadIdx.x;
    if (i < BB * SS * DD) {
        int d = i & (DD - 1);
        g_slots[i] = fmaf(sg[d], noise[i], mu[d]);
    }
}

// ---------------- q projection: qt[b,s,:] = (LN(slots[b,s]) @ Wq^T + bq) @ Wk
__global__ void k_q(const float* __restrict__ Wq, const float* __restrict__ bq,
                    const float* __restrict__ Wk,
                    const float* __restrict__ lg, const float* __restrict__ lb) {
    const int bs = blockIdx.x;   // 0..447
    const int tid = threadIdx.x; // 0..127
    __shared__ float shx[DD];
    __shared__ float shq[DD];
    __shared__ float sred[8];

    float x = g_slots[bs * DD + tid];
    float s1 = x, s2 = x * x;
#pragma unroll
    for (int o = 16; o > 0; o >>= 1) {
        s1 += __shfl_xor_sync(~0u, s1, o);
        s2 += __shfl_xor_sync(~0u, s2, o);
    }
    int w = tid >> 5;
    if ((tid & 31) == 0) { sred[w] = s1; sred[4 + w] = s2; }
    __syncthreads();
    if (tid == 0) {
        float a = sred[0] + sred[1] + sred[2] + sred[3];
        float c = sred[4] + sred[5] + sred[6] + sred[7];
        float mean = a * (1.f / DD);
        float var = c * (1.f / DD) - mean * mean;
        sred[0] = mean;
        sred[1] = rsqrtf(var + 1e-5f);
    }
    __syncthreads();
    float mean = sred[0], rstd = sred[1];
    shx[tid] = fmaf((x - mean) * rstd, lg[tid], lb[tid]);
    __syncthreads();

    float q = bq[tid];
    const float* wr = Wq + tid * DD;
#pragma unroll 8
    for (int e = 0; e < DD; e++) q = fmaf(shx[e], wr[e], q);
    shq[tid] = q;
    __syncthreads();

    float qt = 0.f;
#pragma unroll 8
    for (int d = 0; d < DD; d++) qt = fmaf(shq[d], Wk[d * DD + tid], qt);
    g_qt[bs * DD + tid] = qt;
}

// ---------------- flash pass over N with on-the-fly LN -------------------
// warp-per-row-group: each warp owns 64 rows; lane owns 4 of the 128 dims.
__global__ void __launch_bounds__(256, 2)
k_flash(const float* __restrict__ emb,
        const float* __restrict__ lg, const float* __restrict__ lb) {
    const int lane = threadIdx.x & 31;
    const int wid = threadIdx.x >> 5;
    const int b = blockIdx.y;
    const int wb = blockIdx.x * FLASH_WARPS + wid;  // 0..63

    float4 qt[SS];
#pragma unroll
    for (int s = 0; s < SS; s++)
        qt[s] = *(const float4*)&g_qt[(b * SS + s) * DD + lane * 4];
    const float4 gv = *(const float4*)&lg[lane * 4];
    const float4 bv = *(const float4*)&lb[lane * 4];

    float m[SS], l[SS];
    float4 acc[SS];
    float4 es = make_float4(0.f, 0.f, 0.f, 0.f);
#pragma unroll
    for (int s = 0; s < SS; s++) {
        m[s] = -INFINITY;
        l[s] = 0.f;
        acc[s] = make_float4(0.f, 0.f, 0.f, 0.f);
    }

    const float4* base = (const float4*)emb +
        ((long long)b * NN + (long long)wb * ROWS_PER_WARP) * (DD / 4) + lane;

    float4 x = base[0];
    for (int r = 0; r < ROWS_PER_WARP; r++) {
        float4 xn;
        if (r + 1 < ROWS_PER_WARP) xn = base[(r + 1) * (DD / 4)];
        // row mean/var (warp reduce)
        float s1 = x.x + x.y + x.z + x.w;
        float s2 = fmaf(x.x, x.x, fmaf(x.y, x.y, fmaf(x.z, x.z, x.w * x.w)));
#pragma unroll
        for (int o = 16; o > 0; o >>= 1) {
            s1 += __shfl_xor_sync(~0u, s1, o);
            s2 += __shfl_xor_sync(~0u, s2, o);
        }
        float mean = s1 * (1.f / DD);
        float rstd = rsqrtf(fmaf(-mean, mean, s2 * (1.f / DD)) + 1e-5f);
        float4 e;
        e.x = fmaf((x.x - mean) * rstd, gv.x, bv.x);
        e.y = fmaf((x.y - mean) * rstd, gv.y, bv.y);
        e.z = fmaf((x.z - mean) * rstd, gv.z, bv.z);
        e.w = fmaf((x.w - mean) * rstd, gv.w, bv.w);
        es.x += e.x; es.y += e.y; es.z += e.z; es.w += e.w;

        // 7 logits (qt . e_ln), warp reduced
        float z[SS];
#pragma unroll
        for (int s = 0; s < SS; s++) {
            float t = fmaf(e.x, qt[s].x,
                     fmaf(e.y, qt[s].y,
                     fmaf(e.z, qt[s].z, e.w * qt[s].w)));
#pragma unroll
            for (int o = 16; o > 0; o >>= 1) t += __shfl_xor_sync(~0u, t, o);
            z[s] = t;
        }
        // online softmax update (branch is warp-uniform)
#pragma unroll
        for (int s = 0; s < SS; s++) {
            float zz = z[s];
            if (zz <= m[s]) {
                float p = __expf(zz - m[s]);
                l[s] += p;
                acc[s].x = fmaf(p, e.x, acc[s].x);
                acc[s].y = fmaf(p, e.y, acc[s].y);
                acc[s].z = fmaf(p, e.z, acc[s].z);
                acc[s].w = fmaf(p, e.w, acc[s].w);
            } else {
                float sc = __expf(m[s] - zz);
                m[s] = zz;
                l[s] = fmaf(l[s], sc, 1.f);
                acc[s].x = fmaf(acc[s].x, sc, e.x);
                acc[s].y = fmaf(acc[s].y, sc, e.y);
                acc[s].z = fmaf(acc[s].z, sc, e.z);
                acc[s].w = fmaf(acc[s].w, sc, e.w);
            }
        }
        x = xn;
    }

    const int pidx = b * NW + wb;
#pragma unroll
    for (int s = 0; s < SS; s++)
        *(float4*)&g_pacc[(pidx * SS + s) * DD + lane * 4] = acc[s];
    *(float4*)&g_pes[pidx * DD + lane * 4] = es;
    if (lane == 0) {
#pragma unroll
        for (int s = 0; s < SS; s++) {
            g_pm[pidx * SS + s] = m[s];
            g_pl[pidx * SS + s] = l[s];
        }
    }
}

// ---------------- combine partials + updates + GRU + FF ------------------
// one block per batch, 896 threads: thread = (s, d)
__global__ void __launch_bounds__(896)
k_up(const float* __restrict__ Wv, const float* __restrict__ bvv,
     const float* __restrict__ Wih, const float* __restrict__ Whh,
     const float* __restrict__ bih, const float* __restrict__ bhh,
     const float* __restrict__ W1, const float* __restrict__ b1,
     const float* __restrict__ W2, const float* __restrict__ b2,
     const float* __restrict__ lg, const float* __restrict__ lb,
     float* __restrict__ out, int last) {
    const int b = blockIdx.x;
    const int t = threadIdx.x;  // 0..895
    const int s = t >> 7;       // 0..6
    const int d = t & 127;

    __shared__ float su[SS * DD];
    __shared__ float sx[SS * DD];
    __shared__ float sh2[SS * DD];
    __shared__ float sn[SS * DD];
    __shared__ float sf[SS * HH];
    __shared__ float SW[NW * SS];
    __shared__ float SM[SS], SL[SS];
    __shared__ float ES[DD];
    __shared__ float smean[SS], srstd[SS];

    // A1: global max per s
    if (t < SS) {
        float mm = -INFINITY;
        for (int sp = 0; sp < NW; sp++)
            mm = fmaxf(mm, g_pm[(b * NW + sp) * SS + t]);
        SM[t] = mm;
    }
    __syncthreads();
    // A2: merge weights
    if (t < NW * SS) {
        int sp = t / SS, ss = t - sp * SS;
        SW[t] = __expf(g_pm[(b * NW + sp) * SS + ss] - SM[ss]);
    }
    __syncthreads();
    // A3: total denominators (threads 0..6)
    if (t < SS) {
        float L = 0.f;
        for (int sp = 0; sp < NW; sp++)
            L += g_pl[(b * NW + sp) * SS + t] * SW[sp * SS + t];
        SL[t] = L;
    }
    // A4: e_ln column sums (threads 128..255)
    if (t >= 128 && t < 256) {
        int e = t - 128;
        float sum = 0.f;
        for (int sp = 0; sp < NW; sp++) sum += g_pes[(b * NW + sp) * DD + e];
        ES[e] = sum;
    }
    // A5: merged numerator for this (s,d)
    float accv = 0.f;
#pragma unroll 4
    for (int sp = 0; sp < NW; sp++)
        accv = fmaf(g_pacc[((b * NW + sp) * SS + s) * DD + d], SW[sp * SS + s], accv);
    __syncthreads();
    const float invC = 1.f / (1.f + (float)NN * 1e-8f);
    su[t] = (accv / SL[s] + 1e-8f * ES[d]) * invC;   // u = attn @ e_ln (exact, incl. EPS)
    __syncthreads();

    // B: updates = u @ Wv^T + bv ; load h
    {
        float u0 = bvv[d];
        const float* wr = Wv + d * DD;
        const float* ur = su + s * DD;
#pragma unroll 4
        for (int e = 0; e < DD; e++) u0 = fmaf(ur[e], wr[e], u0);
        sx[t] = u0;
        sh2[t] = g_slots[(b * SS + s) * DD + d];
    }
    __syncthreads();

    // C: GRU cell (pytorch gate order r,z,n)
    {
        float gir = bih[d], giz = bih[DD + d], gin = bih[2 * DD + d];
        float ghr = bhh[d], ghz = bhh[DD + d], ghn = bhh[2 * DD + d];
        const float* wi_r = Wih + d * DD;
        const float* wi_z = Wih + (DD + d) * DD;
        const float* wi_n = Wih + (2 * DD + d) * DD;
        const float* wh_r = Whh + d * DD;
        const float* wh_z = Whh + (DD + d) * DD;
        const float* wh_n = Whh + (2 * DD + d) * DD;
        const float* xr = sx + s * DD;
        const float* hr = sh2 + s * DD;
#pragma unroll 4
        for (int e = 0; e < DD; e++) {
            float xv = xr[e], hv = hr[e];
            gir = fmaf(xv, wi_r[e], gir);
            giz = fmaf(xv, wi_z[e], giz);
            gin = fmaf(xv, wi_n[e], gin);
            ghr = fmaf(hv, wh_r[e], ghr);
            ghz = fmaf(hv, wh_z[e], ghz);
            ghn = fmaf(hv, wh_n[e], ghn);
        }
        float r = 1.f / (1.f + expf(-(gir + ghr)));
        float zz = 1.f / (1.f + expf(-(giz + ghz)));
        float n = tanhf(fmaf(r, ghn, gin));
        sn[t] = fmaf(zz, sh2[t] - n, n);  // (1-z)n + z*h
    }
    __syncthreads();

    // D: LN over new slots (warp per row)
    {
        int w = t >> 5;
        if (w < SS) {
            int ln = t & 31;
            float a = 0.f, c = 0.f;
#pragma unroll
            for (int k = 0; k < 4; k++) {
                float v = sn[w * DD + ln * 4 + k];
                a += v;
                c = fmaf(v, v, c);
            }
#pragma unroll
            for (int o = 16; o > 0; o >>= 1) {
                a += __shfl_xor_sync(~0u, a, o);
                c += __shfl_xor_sync(~0u, c, o);
            }
            if (ln == 0) {
                float mean = a * (1.f / DD);
                smean[w] = mean;
                srstd[w] = rsqrtf(c * (1.f / DD) - mean * mean + 1e-5f);
            }
        }
    }
    __syncthreads();
    su[t] = fmaf((sn[t] - smean[s]) * srstd[s], lg[d], lb[d]);  // reuse su as LN(slots)
    __syncthreads();

    // E: FF1 (relu)
    for (int idx = t; idx < SS * HH; idx += 896) {
        int ss = idx >> 8;
        int hh = idx & 255;
        float f = b1[hh];
        const float* wr = W1 + hh * DD;
        const float* ur = su + ss * DD;
#pragma unroll 4
        for (int e = 0; e < DD; e++) f = fmaf(ur[e], wr[e], f);
        sf[idx] = fmaxf(f, 0.f);
    }
    __syncthreads();

    // F: FF2 + residual + write
    {
        float o = b2[d];
        const float* wr = W2 + d * HH;
        const float* fr = sf + s * HH;
#pragma unroll 4
        for (int hh = 0; hh < HH; hh++) o = fmaf(fr[hh], wr[hh], o);
        float res = sn[t] + o;
        g_slots[(b * SS + s) * DD + d] = res;
        if (last) out[(b * SS + s) * DD + d] = res;
    }
}

// ---------------- launch ----------------
extern "C" void kernel_launch(void* const* d_in, const int* in_sizes, int n_in,
                              void* d_out, int out_size) {
    (void)in_sizes; (void)n_in; (void)out_size;
    const float* emb   = (const float*)d_in[0];
    const float* noise = (const float*)d_in[1];
    const float* mu    = (const float*)d_in[2];
    const float* sg    = (const float*)d_in[3];
    const float* Wk    = (const float*)d_in[4];
    /* bk = d_in[5] — provably unused: a per-(b,s) constant logit shift cancels in softmax */
    const float* Wq    = (const float*)d_in[6];
    const float* bq    = (const float*)d_in[7];
    const float* Wv    = (const float*)d_in[8];
    const float* bvv   = (const float*)d_in[9];
    const float* Wih   = (const float*)d_in[10];
    const float* Whh   = (const float*)d_in[11];
    const float* bih   = (const float*)d_in[12];
    const float* bhh   = (const float*)d_in[13];
    const float* W1    = (const float*)d_in[14];
    const float* b1    = (const float*)d_in[15];
    const float* W2    = (const float*)d_in[16];
    const float* b2    = (const float*)d_in[17];
    const float* lin_g = (const float*)d_in[18];
    const float* lin_b = (const float*)d_in[19];
    const float* ls_g  = (const float*)d_in[20];
    const float* ls_b  = (const float*)d_in[21];
    const float* lf_g  = (const float*)d_in[22];
    const float* lf_b  = (const float*)d_in[23];
    float* out = (float*)d_out;

    k_init<<<(BB * SS * DD + 255) / 256, 256>>>(noise, mu, sg);
    for (int it = 0; it < 3; it++) {
        k_q<<<BB * SS, DD>>>(Wq, bq, Wk, ls_g, ls_b);
        dim3 g(FLASH_BLOCKS_PER_B, BB);
        k_flash<<<g, 256>>>(emb, lin_g, lin_b);
        k_up<<<BB, 896>>>(Wv, bvv, Wih, Whh, bih, bhh,
                          W1, b1, W2, b2, lf_g, lf_b, out, it == 2);
    }
}

// round 3
// speedup vs baseline: 2.8745x; 2.8745x over previous
#include <cuda_runtime.h>
#include <math.h>

#define BB 64
#define NN 4096
#define DD 128
#define SS 7
#define HH 256
#define NW 64                    // warp-partials per batch
#define ROWS_PER_WARP (NN / NW)  // 64
#define FLASH_WARPS 4
#define FLASH_BLOCKS_PER_B (NW / FLASH_WARPS)  // 16

// ---------------- device scratch (no allocations allowed) ----------------
__device__ __align__(16) float g_slots[BB * SS * DD];
__device__ __align__(16) float g_qt[BB * SS * DD];
__device__ __align__(16) float g_pm[BB * NW * SS];
__device__ __align__(16) float g_pl[BB * NW * SS];
__device__ __align__(16) float g_pacc[BB * NW * SS * DD];   // ~14.7 MB
__device__ __align__(16) float g_pes[BB * NW * DD];
// transposed weights: WT[in * O + out]
__device__ __align__(16) float g_WqT[DD * DD];
__device__ __align__(16) float g_WvT[DD * DD];
__device__ __align__(16) float g_WihT[DD * 3 * DD];
__device__ __align__(16) float g_WhhT[DD * 3 * DD];
__device__ __align__(16) float g_W1T[DD * HH];
__device__ __align__(16) float g_W2T[HH * DD];

// ---------------- slot init: slots = mu + sigma * noise ----------------
__global__ void k_init(const float* __restrict__ noise,
                       const float* __restrict__ mu,
                       const float* __restrict__ sg) {
    int i = blockIdx.x * blockDim.x + threadIdx.x;
    if (i < BB * SS * DD) {
        int d = i & (DD - 1);
        g_slots[i] = fmaf(sg[d], noise[i], mu[d]);
    }
}

// ---------------- tiled transpose: dst[i*O+o] = src[o*I+i] ----------------
__global__ void k_tr(const float* __restrict__ src, int which, int O, int I) {
    float* dst = (which == 0) ? g_WqT :
                 (which == 1) ? g_WvT :
                 (which == 2) ? g_WihT :
                 (which == 3) ? g_WhhT :
                 (which == 4) ? g_W1T : g_W2T;
    __shared__ float tile[32][33];
    int i0 = blockIdx.x * 32, o0 = blockIdx.y * 32;
#pragma unroll
    for (int k = 0; k < 32; k += 8) {
        int o = o0 + threadIdx.y + k, i = i0 + threadIdx.x;
        if (o < O && i < I) tile[threadIdx.y + k][threadIdx.x] = src[o * I + i];
    }
    __syncthreads();
#pragma unroll
    for (int k = 0; k < 32; k += 8) {
        int o = o0 + threadIdx.x, i = i0 + threadIdx.y + k;
        if (i < I && o < O) dst[i * O + o] = tile[threadIdx.x][threadIdx.y + k];
    }
}

// ---------------- initial q projection (iter 0) --------------------------
// qt[b,s,:] = ((LN_s(slots) @ Wq^T + bq) @ Wk)
__global__ void __launch_bounds__(128)
k_q0(const float* __restrict__ bq, const float* __restrict__ Wk,
     const float* __restrict__ lg, const float* __restrict__ lb) {
    const int bs = blockIdx.x;
    const int d = threadIdx.x;
    __shared__ float lnq[DD], sq[DD], red[8];

    float x = g_slots[bs * DD + d];
    float a = x, c = x * x;
#pragma unroll
    for (int o = 16; o > 0; o >>= 1) {
        a += __shfl_xor_sync(~0u, a, o);
        c += __shfl_xor_sync(~0u, c, o);
    }
    if ((d & 31) == 0) { red[d >> 5] = a; red[4 + (d >> 5)] = c; }
    __syncthreads();
    float mean = (red[0] + red[1] + red[2] + red[3]) * (1.f / DD);
    float msq = (red[4] + red[5] + red[6] + red[7]) * (1.f / DD);
    float rstd = rsqrtf(msq - mean * mean + 1e-5f);
    lnq[d] = fmaf((x - mean) * rstd, lg[d], lb[d]);
    __syncthreads();

    float q = bq[d];
#pragma unroll 8
    for (int e = 0; e < DD; e++) q = fmaf(lnq[e], g_WqT[e * DD + d], q);
    sq[d] = q;
    __syncthreads();
    float qt = 0.f;
#pragma unroll 8
    for (int e = 0; e < DD; e++) qt = fmaf(sq[e], Wk[e * DD + d], qt);
    g_qt[bs * DD + d] = qt;
}

// ---------------- flash pass over N with on-the-fly LN -------------------
__global__ void __launch_bounds__(128, 4)
k_flash(const float* __restrict__ emb,
        const float* __restrict__ lg, const float* __restrict__ lb) {
    const int lane = threadIdx.x & 31;
    const int wid = threadIdx.x >> 5;
    const int b = blockIdx.y;
    const int wb = blockIdx.x * FLASH_WARPS + wid;  // 0..63

    float4 qt[SS];
#pragma unroll
    for (int s = 0; s < SS; s++)
        qt[s] = *(const float4*)&g_qt[(b * SS + s) * DD + lane * 4];
    const float4 gv = *(const float4*)&lg[lane * 4];
    const float4 bv = *(const float4*)&lb[lane * 4];

    float m[SS], l[SS];
    float4 acc[SS];
    float4 es = make_float4(0.f, 0.f, 0.f, 0.f);
#pragma unroll
    for (int s = 0; s < SS; s++) {
        m[s] = -INFINITY;
        l[s] = 0.f;
        acc[s] = make_float4(0.f, 0.f, 0.f, 0.f);
    }

    const float4* base = (const float4*)emb +
        ((long long)b * NN + (long long)wb * ROWS_PER_WARP) * (DD / 4) + lane;

    float4 x = base[0];
    for (int r = 0; r < ROWS_PER_WARP; r++) {
        float4 xn;
        if (r + 1 < ROWS_PER_WARP) xn = base[(r + 1) * (DD / 4)];
        float s1 = x.x + x.y + x.z + x.w;
        float s2 = fmaf(x.x, x.x, fmaf(x.y, x.y, fmaf(x.z, x.z, x.w * x.w)));
#pragma unroll
        for (int o = 16; o > 0; o >>= 1) {
            s1 += __shfl_xor_sync(~0u, s1, o);
            s2 += __shfl_xor_sync(~0u, s2, o);
        }
        float mean = s1 * (1.f / DD);
        float rstd = rsqrtf(fmaf(-mean, mean, s2 * (1.f / DD)) + 1e-5f);
        float4 e;
        e.x = fmaf((x.x - mean) * rstd, gv.x, bv.x);
        e.y = fmaf((x.y - mean) * rstd, gv.y, bv.y);
        e.z = fmaf((x.z - mean) * rstd, gv.z, bv.z);
        e.w = fmaf((x.w - mean) * rstd, gv.w, bv.w);
        es.x += e.x; es.y += e.y; es.z += e.z; es.w += e.w;

        float z[SS];
#pragma unroll
        for (int s = 0; s < SS; s++) {
            float t = fmaf(e.x, qt[s].x,
                     fmaf(e.y, qt[s].y,
                     fmaf(e.z, qt[s].z, e.w * qt[s].w)));
#pragma unroll
            for (int o = 16; o > 0; o >>= 1) t += __shfl_xor_sync(~0u, t, o);
            z[s] = t;
        }
#pragma unroll
        for (int s = 0; s < SS; s++) {
            float zz = z[s];
            if (zz <= m[s]) {
                float p = __expf(zz - m[s]);
                l[s] += p;
                acc[s].x = fmaf(p, e.x, acc[s].x);
                acc[s].y = fmaf(p, e.y, acc[s].y);
                acc[s].z = fmaf(p, e.z, acc[s].z);
                acc[s].w = fmaf(p, e.w, acc[s].w);
            } else {
                float sc = __expf(m[s] - zz);
                m[s] = zz;
                l[s] = fmaf(l[s], sc, 1.f);
                acc[s].x = fmaf(acc[s].x, sc, e.x);
                acc[s].y = fmaf(acc[s].y, sc, e.y);
                acc[s].z = fmaf(acc[s].z, sc, e.z);
                acc[s].w = fmaf(acc[s].w, sc, e.w);
            }
        }
        x = xn;
    }

    const int pidx = b * NW + wb;
#pragma unroll
    for (int s = 0; s < SS; s++)
        *(float4*)&g_pacc[(pidx * SS + s) * DD + lane * 4] = acc[s];
    *(float4*)&g_pes[pidx * DD + lane * 4] = es;
    if (lane == 0) {
#pragma unroll
        for (int s = 0; s < SS; s++) {
            g_pm[pidx * SS + s] = m[s];
            g_pl[pidx * SS + s] = l[s];
        }
    }
}

// ---------------- combine + updates + GRU + FF + next-q ------------------
// one block per (b,s) row, 128 threads (thread = output dim d)
__global__ void __launch_bounds__(128)
k_up(const float* __restrict__ bvv,
     const float* __restrict__ bih, const float* __restrict__ bhh,
     const float* __restrict__ b1, const float* __restrict__ b2,
     const float* __restrict__ lfg, const float* __restrict__ lfb,
     const float* __restrict__ bq, const float* __restrict__ Wk,
     const float* __restrict__ lsg, const float* __restrict__ lsb,
     float* __restrict__ out, int last) {
    const int b = blockIdx.x / SS;
    const int s = blockIdx.x % SS;
    const int d = threadIdx.x;
    const int w = d >> 5, ln = d & 31;

    __shared__ float su[DD], sx[DD], shh[DD], lnv[DD], sf[HH], sw[NW];
    __shared__ float red[8];

    // ---- A: merge flash partials ----
    float pmv = -INFINITY, plv = 0.f;
    if (d < NW) {
        pmv = g_pm[(b * NW + d) * SS + s];
        plv = g_pl[(b * NW + d) * SS + s];
    }
    float mm = pmv;
#pragma unroll
    for (int o = 16; o > 0; o >>= 1) mm = fmaxf(mm, __shfl_xor_sync(~0u, mm, o));
    if (ln == 0) red[w] = mm;
    __syncthreads();
    float M = fmaxf(fmaxf(red[0], red[1]), fmaxf(red[2], red[3]));
    float wgt = (d < NW) ? __expf(pmv - M) : 0.f;
    if (d < NW) sw[d] = wgt;
    float lw = plv * wgt;
#pragma unroll
    for (int o = 16; o > 0; o >>= 1) lw += __shfl_xor_sync(~0u, lw, o);
    __syncthreads();                 // red reuse + sw visibility
    if (ln == 0) red[w] = lw;
    __syncthreads();
    float L = red[0] + red[1] + red[2] + red[3];

    float accv = 0.f, esv = 0.f;
    const float* pa = g_pacc + ((long long)(b * NW) * SS + s) * DD + d;
    const float* pe = g_pes + (long long)(b * NW) * DD + d;
#pragma unroll 4
    for (int sp = 0; sp < NW; sp++) {
        accv = fmaf(pa[sp * SS * DD], sw[sp], accv);
        esv += pe[sp * DD];
    }
    const float invC = 1.f / (1.f + (float)NN * 1e-8f);
    su[d] = (accv / L + 1e-8f * esv) * invC;      // u = attn @ e_ln (exact EPS)
    float h = g_slots[(b * SS + s) * DD + d];
    shh[d] = h;
    __syncthreads();

    // ---- B: updates = u @ Wv^T + bv ----
    float xv = bvv[d];
#pragma unroll 8
    for (int e = 0; e < DD; e++) xv = fmaf(su[e], g_WvT[e * DD + d], xv);
    sx[d] = xv;
    __syncthreads();

    // ---- C: GRU (pytorch gate order r,z,n) ----
    float gir = bih[d], giz = bih[DD + d], gin = bih[2 * DD + d];
    float ghr = bhh[d], ghz = bhh[DD + d], ghn = bhh[2 * DD + d];
#pragma unroll 4
    for (int e = 0; e < DD; e++) {
        float xe = sx[e], he = shh[e];
        const float* wi = g_WihT + e * 3 * DD + d;
        const float* wh = g_WhhT + e * 3 * DD + d;
        gir = fmaf(xe, wi[0], gir);
        giz = fmaf(xe, wi[DD], giz);
        gin = fmaf(xe, wi[2 * DD], gin);
        ghr = fmaf(he, wh[0], ghr);
        ghz = fmaf(he, wh[DD], ghz);
        ghn = fmaf(he, wh[2 * DD], ghn);
    }
    float r = 1.f / (1.f + expf(-(gir + ghr)));
    float z = 1.f / (1.f + expf(-(giz + ghz)));
    float n = tanhf(fmaf(r, ghn, gin));
    float sv = fmaf(z, h - n, n);                  // new slot (pre-FF)

    // ---- D: LN_ff (block reduce) ----
    {
        float a = sv, c = sv * sv;
#pragma unroll
        for (int o = 16; o > 0; o >>= 1) {
            a += __shfl_xor_sync(~0u, a, o);
            c += __shfl_xor_sync(~0u, c, o);
        }
        __syncthreads();             // red reuse
        if (ln == 0) { red[w] = a; red[4 + w] = c; }
        __syncthreads();
        float mean = (red[0] + red[1] + red[2] + red[3]) * (1.f / DD);
        float msq = (red[4] + red[5] + red[6] + red[7]) * (1.f / DD);
        float rstd = rsqrtf(msq - mean * mean + 1e-5f);
        lnv[d] = fmaf((sv - mean) * rstd, lfg[d], lfb[d]);
    }
    __syncthreads();

    // ---- E: FF1 (relu), 2 outputs per thread ----
    float f1 = b1[d], f2 = b1[DD + d];
#pragma unroll 8
    for (int e = 0; e < DD; e++) {
        float le = lnv[e];
        f1 = fmaf(le, g_W1T[e * HH + d], f1);
        f2 = fmaf(le, g_W1T[e * HH + DD + d], f2);
    }
    sf[d] = fmaxf(f1, 0.f);
    sf[DD + d] = fmaxf(f2, 0.f);
    __syncthreads();

    // ---- F: FF2 + residual ----
    float o2 = b2[d];
#pragma unroll 8
    for (int hh = 0; hh < HH; hh++) o2 = fmaf(sf[hh], g_W2T[hh * DD + d], o2);
    float res = sv + o2;
    g_slots[(b * SS + s) * DD + d] = res;
    if (last) {
        out[(b * SS + s) * DD + d] = res;
    } else {
        // ---- G: q projection for next iteration ----
        float a = res, c = res * res;
#pragma unroll
        for (int o = 16; o > 0; o >>= 1) {
            a += __shfl_xor_sync(~0u, a, o);
            c += __shfl_xor_sync(~0u, c, o);
        }
        __syncthreads();             // red reuse
        if (ln == 0) { red[w] = a; red[4 + w] = c; }
        __syncthreads();
        float mean = (red[0] + red[1] + red[2] + red[3]) * (1.f / DD);
        float msq = (red[4] + red[5] + red[6] + red[7]) * (1.f / DD);
        float rstd = rsqrtf(msq - mean * mean + 1e-5f);
        su[d] = fmaf((res - mean) * rstd, lsg[d], lsb[d]);
        __syncthreads();
        float q = bq[d];
#pragma unroll 8
        for (int e = 0; e < DD; e++) q = fmaf(su[e], g_WqT[e * DD + d], q);
        sx[d] = q;
        __syncthreads();
        float qt = 0.f;
#pragma unroll 8
        for (int e = 0; e < DD; e++) qt = fmaf(sx[e], Wk[e * DD + d], qt);
        g_qt[(b * SS + s) * DD + d] = qt;
    }
}

// ---------------- launch ----------------
extern "C" void kernel_launch(void* const* d_in, const int* in_sizes, int n_in,
                              void* d_out, int out_size) {
    (void)in_sizes; (void)n_in; (void)out_size;
    const float* emb   = (const float*)d_in[0];
    const float* noise = (const float*)d_in[1];
    const float* mu    = (const float*)d_in[2];
    const float* sg    = (const float*)d_in[3];
    const float* Wk    = (const float*)d_in[4];
    /* bk = d_in[5] unused: constant per-(b,s) logit shift cancels in softmax */
    const float* Wq    = (const float*)d_in[6];
    const float* bq    = (const float*)d_in[7];
    const float* Wv    = (const float*)d_in[8];
    const float* bvv   = (const float*)d_in[9];
    const float* Wih   = (const float*)d_in[10];
    const float* Whh   = (const float*)d_in[11];
    const float* bih   = (const float*)d_in[12];
    const float* bhh   = (const float*)d_in[13];
    const float* W1    = (const float*)d_in[14];
    const float* b1    = (const float*)d_in[15];
    const float* W2    = (const float*)d_in[16];
    const float* b2    = (const float*)d_in[17];
    const float* lin_g = (const float*)d_in[18];
    const float* lin_b = (const float*)d_in[19];
    const float* ls_g  = (const float*)d_in[20];
    const float* ls_b  = (const float*)d_in[21];
    const float* lf_g  = (const float*)d_in[22];
    const float* lf_b  = (const float*)d_in[23];
    float* out = (float*)d_out;

    k_init<<<(BB * SS * DD + 255) / 256, 256>>>(noise, mu, sg);
    dim3 trb(32, 8);
    k_tr<<<dim3(4, 4),  trb>>>(Wq, 0, DD, DD);
    k_tr<<<dim3(4, 4),  trb>>>(Wv, 1, DD, DD);
    k_tr<<<dim3(4, 12), trb>>>(Wih, 2, 3 * DD, DD);
    k_tr<<<dim3(4, 12), trb>>>(Whh, 3, 3 * DD, DD);
    k_tr<<<dim3(4, 8),  trb>>>(W1, 4, HH, DD);
    k_tr<<<dim3(8, 4),  trb>>>(W2, 5, DD, HH);
    k_q0<<<BB * SS, DD>>>(bq, Wk, ls_g, ls_b);
    for (int it = 0; it < 3; it++) {
        dim3 g(FLASH_BLOCKS_PER_B, BB);
        k_flash<<<g, 128>>>(emb, lin_g, lin_b);
        k_up<<<BB * SS, DD>>>(bvv, bih, bhh, b1, b2, lf_g, lf_b,
                              bq, Wk, ls_g, ls_b, out, it == 2);
    }
}

// round 7
// speedup vs baseline: 3.0724x; 1.0688x over previous
#include <cuda_runtime.h>
#include <math.h>

#define BB 64
#define NN 4096
#define DD 128
#define SS 7
#define HH 256
#define NW 64                    // warp-partials per batch
#define RPW 64                   // rows per warp
#define EPSV 1e-8f

// ---------------- device scratch ----------------
__device__ __align__(16) float g_slots[BB * SS * DD];
__device__ __align__(16) float g_wq[BB * SS * DD];     // qt ∘ lin_g
__device__ float g_ws[BB * SS];                        // Σ (qt∘lin_g)
__device__ float g_c1[BB * SS];                        // qt · lin_b
__device__ __align__(16) float g_mv[BB * NN * 2];      // per-row (mean, rstd)
__device__ __align__(16) float g_es[BB * DD];          // per-batch Σ e_ln
__device__ __align__(16) float g_pesx[BB * NW * DD];
__device__ float g_pesm[BB * NW];
__device__ float g_pm[BB * NW * SS];
__device__ float g_pl[BB * NW * SS];
__device__ float g_pam[BB * NW * SS];
__device__ __align__(16) float g_pax[BB * NW * SS * DD];
// transposed weights: WT[in * O + out]
__device__ __align__(16) float g_WqT[DD * DD];
__device__ __align__(16) float g_WvT[DD * DD];
__device__ __align__(16) float g_WihT[DD * 3 * DD];
__device__ __align__(16) float g_WhhT[DD * 3 * DD];
__device__ __align__(16) float g_W1T[DD * HH];
__device__ __align__(16) float g_W2T[HH * DD];

// ---------------- slot init ----------------
__global__ void k_init(const float* __restrict__ noise,
                       const float* __restrict__ mu,
                       const float* __restrict__ sg) {
    int i = blockIdx.x * blockDim.x + threadIdx.x;
    if (i < BB * SS * DD) {
        int d = i & (DD - 1);
        g_slots[i] = fmaf(sg[d], noise[i], mu[d]);
    }
}

// ---------------- fused transpose of all 6 weight matrices ---------------
__global__ void k_tr_all(const float* __restrict__ Wq, const float* __restrict__ Wv,
                         const float* __restrict__ Wih, const float* __restrict__ Whh,
                         const float* __restrict__ W1, const float* __restrict__ W2) {
    int id = blockIdx.x;
    const float* src; float* dst; int O, I, ti, to;
    if (id < 16)       { src = Wq;  dst = g_WqT;  O = DD;     I = DD; ti = id & 3; to = id >> 2; }
    else if (id < 32)  { id -= 16;  src = Wv;  dst = g_WvT;  O = DD;     I = DD; ti = id & 3; to = id >> 2; }
    else if (id < 80)  { id -= 32;  src = Wih; dst = g_WihT; O = 3 * DD; I = DD; ti = id & 3; to = id >> 2; }
    else if (id < 128) { id -= 80;  src = Whh; dst = g_WhhT; O = 3 * DD; I = DD; ti = id & 3; to = id >> 2; }
    else if (id < 160) { id -= 128; src = W1;  dst = g_W1T;  O = HH;     I = DD; ti = id & 3; to = id >> 2; }
    else               { id -= 160; src = W2;  dst = g_W2T;  O = DD;     I = HH; ti = id & 7; to = id >> 3; }
    __shared__ float tile[32][33];
    int i0 = ti * 32, o0 = to * 32;
#pragma unroll
    for (int k = 0; k < 32; k += 8) {
        int o = o0 + threadIdx.y + k, i = i0 + threadIdx.x;
        tile[threadIdx.y + k][threadIdx.x] = src[o * I + i];
    }
    __syncthreads();
#pragma unroll
    for (int k = 0; k < 32; k += 8) {
        int o = o0 + threadIdx.x, i = i0 + threadIdx.y + k;
        dst[i * O + o] = tile[threadIdx.x][threadIdx.y + k];
    }
}

// ---------------- prep: per-row LN stats + es partials (once) ------------
__global__ void __launch_bounds__(256) k_prep(const float* __restrict__ emb) {
    const int lane = threadIdx.x & 31, wid = threadIdx.x >> 5;
    const int b = blockIdx.y, w = blockIdx.x * 8 + wid;
    const float4* base = (const float4*)emb + (long long)(b * NN + w * RPW) * 32 + lane;
    float2* mvout = (float2*)g_mv + (b * NN + w * RPW);
    float4 esx = make_float4(0.f, 0.f, 0.f, 0.f);
    float esm = 0.f;
    for (int r = 0; r < RPW; r++) {
        float4 x = base[r * 32];
        float s1 = x.x + x.y + x.z + x.w;
        float s2 = fmaf(x.x, x.x, fmaf(x.y, x.y, fmaf(x.z, x.z, x.w * x.w)));
#pragma unroll
        for (int o = 16; o > 0; o >>= 1) {
            s1 += __shfl_xor_sync(~0u, s1, o);
            s2 += __shfl_xor_sync(~0u, s2, o);
        }
        float mean = s1 * (1.f / DD);
        float rstd = rsqrtf(fmaf(-mean, mean, s2 * (1.f / DD)) + 1e-5f);
        if (lane == 0) mvout[r] = make_float2(mean, rstd);
        esx.x = fmaf(rstd, x.x, esx.x);
        esx.y = fmaf(rstd, x.y, esx.y);
        esx.z = fmaf(rstd, x.z, esx.z);
        esx.w = fmaf(rstd, x.w, esx.w);
        esm = fmaf(rstd, mean, esm);
    }
    ((float4*)g_pesx)[(b * NW + w) * 32 + lane] = esx;
    if (lane == 0) g_pesm[b * NW + w] = esm;
}

// ---------------- es finalize: es[b][d] = g*(Σrstd·x − Σrstd·mean) + N·b --
__global__ void k_es(const float* __restrict__ lg, const float* __restrict__ lb) {
    int b = blockIdx.x, d = threadIdx.x;
    float sx = 0.f, sm = 0.f;
    for (int w = 0; w < NW; w++) {
        sx += g_pesx[(b * NW + w) * DD + d];
        sm += g_pesm[b * NW + w];
    }
    g_es[b * DD + d] = lg[d] * (sx - sm) + (float)NN * lb[d];
}

// ---------------- initial q projection (iter 0) --------------------------
__global__ void __launch_bounds__(128)
k_q0(const float* __restrict__ bq, const float* __restrict__ Wk,
     const float* __restrict__ lg, const float* __restrict__ lb,
     const float* __restrict__ ling, const float* __restrict__ linb) {
    const int bs = blockIdx.x;
    const int d = threadIdx.x;
    const int w = d >> 5, ln = d & 31;
    __shared__ float lnq[DD], sq[DD], red[8];

    float x = g_slots[bs * DD + d];
    float a = x, c = x * x;
#pragma unroll
    for (int o = 16; o > 0; o >>= 1) {
        a += __shfl_xor_sync(~0u, a, o);
        c += __shfl_xor_sync(~0u, c, o);
    }
    if (ln == 0) { red[w] = a; red[4 + w] = c; }
    __syncthreads();
    float mean = (red[0] + red[1] + red[2] + red[3]) * (1.f / DD);
    float msq = (red[4] + red[5] + red[6] + red[7]) * (1.f / DD);
    float rstd = rsqrtf(msq - mean * mean + 1e-5f);
    lnq[d] = fmaf((x - mean) * rstd, lg[d], lb[d]);
    __syncthreads();

    float q = bq[d];
#pragma unroll 8
    for (int e = 0; e < DD; e++) q = fmaf(lnq[e], g_WqT[e * DD + d], q);
    sq[d] = q;
    __syncthreads();
    float qt = 0.f;
#pragma unroll 8
    for (int e = 0; e < DD; e++) qt = fmaf(sq[e], Wk[e * DD + d], qt);

    float wqv = qt * ling[d];
    float c1v = qt * linb[d];
    g_wq[bs * DD + d] = wqv;
    float aa = wqv, cc = c1v;
#pragma unroll
    for (int o = 16; o > 0; o >>= 1) {
        aa += __shfl_xor_sync(~0u, aa, o);
        cc += __shfl_xor_sync(~0u, cc, o);
    }
    __syncthreads();
    if (ln == 0) { red[w] = aa; red[4 + w] = cc; }
    __syncthreads();
    if (d == 0) {
        g_ws[bs] = red[0] + red[1] + red[2] + red[3];
        g_c1[bs] = red[4] + red[5] + red[6] + red[7];
    }
}

// ---------------- flash: lane-per-row logits, x-space accumulation -------
__global__ void __launch_bounds__(32)
k_flash(const float* __restrict__ emb) {
    __shared__ float4 xt[32][33];       // 32 rows x 128 floats, padded
    __shared__ float4 wqs[SS][32];      // wq vectors
    __shared__ float ps[32][12];        // per-row probs*rstd (7 + pad)
    const int lane = threadIdx.x;
    const int b = blockIdx.y, w = blockIdx.x;

#pragma unroll
    for (int s = 0; s < SS; s++)
        wqs[s][lane] = ((const float4*)g_wq)[(b * SS + s) * 32 + lane];
    float ws[SS], c1[SS];
#pragma unroll
    for (int s = 0; s < SS; s++) {
        ws[s] = g_ws[b * SS + s];
        c1[s] = g_c1[b * SS + s];
    }

    float m[SS], lsum[SS], amsum[SS];
    float4 acc[SS];
#pragma unroll
    for (int s = 0; s < SS; s++) {
        m[s] = -INFINITY; lsum[s] = 0.f; amsum[s] = 0.f;
        acc[s] = make_float4(0.f, 0.f, 0.f, 0.f);
    }
    const float4* gbase = (const float4*)emb + (long long)(b * NN + w * RPW) * 32;
    const float2* mvb = (const float2*)g_mv + (b * NN + w * RPW);
    __syncwarp();

    for (int t = 0; t < RPW / 32; t++) {
        // stage 32 rows (coalesced: warp loads one full row per iteration)
#pragma unroll 8
        for (int k = 0; k < 32; k++)
            xt[k][lane] = gbase[(t * 32 + k) * 32 + lane];
        float2 mv = mvb[t * 32 + lane];
        __syncwarp();

        // logits for own row (row = lane)
        float z[SS];
#pragma unroll
        for (int s = 0; s < SS; s++) z[s] = 0.f;
#pragma unroll 4
        for (int e = 0; e < 32; e++) {
            float4 xv = xt[lane][e];
#pragma unroll
            for (int s = 0; s < SS; s++) {
                float4 wv = wqs[s][e];
                z[s] = fmaf(xv.x, wv.x, fmaf(xv.y, wv.y,
                       fmaf(xv.z, wv.z, fmaf(xv.w, wv.w, z[s]))));
            }
        }
#pragma unroll
        for (int s = 0; s < SS; s++)
            z[s] = fmaf(mv.y, fmaf(-mv.x, ws[s], z[s]), c1[s]);

        // warp max per s + rescale running state (warp-uniform branch)
#pragma unroll
        for (int s = 0; s < SS; s++) {
            float zm = z[s];
#pragma unroll
            for (int o = 16; o > 0; o >>= 1)
                zm = fmaxf(zm, __shfl_xor_sync(~0u, zm, o));
            if (zm > m[s]) {
                float sc = __expf(m[s] - zm);
                m[s] = zm;
                lsum[s] *= sc;
                amsum[s] *= sc;
                acc[s].x *= sc; acc[s].y *= sc; acc[s].z *= sc; acc[s].w *= sc;
            }
        }
        // probs for own row
        float pr[SS];
#pragma unroll
        for (int s = 0; s < SS; s++) {
            float pv = __expf(z[s] - m[s]);
            lsum[s] += pv;
            pr[s] = pv * mv.y;                       // p * rstd
            amsum[s] = fmaf(pr[s], mv.x, amsum[s]);  // + p*rstd*mean
        }
        *(float4*)&ps[lane][0] = make_float4(pr[0], pr[1], pr[2], pr[3]);
        *(float4*)&ps[lane][4] = make_float4(pr[4], pr[5], pr[6], 0.f);
        __syncwarp();

        // accumulate: acc[s][chunk] += Σ_r pr[r][s] * x[r][chunk]
#pragma unroll 4
        for (int r = 0; r < 32; r++) {
            float4 xv = xt[r][lane];
            float4 pa = *(const float4*)&ps[r][0];
            float4 pb = *(const float4*)&ps[r][4];
            float prv[SS] = {pa.x, pa.y, pa.z, pa.w, pb.x, pb.y, pb.z};
#pragma unroll
            for (int s = 0; s < SS; s++) {
                acc[s].x = fmaf(prv[s], xv.x, acc[s].x);
                acc[s].y = fmaf(prv[s], xv.y, acc[s].y);
                acc[s].z = fmaf(prv[s], xv.z, acc[s].z);
                acc[s].w = fmaf(prv[s], xv.w, acc[s].w);
            }
        }
        __syncwarp();
    }

    // reduce per-lane partials
#pragma unroll
    for (int s = 0; s < SS; s++) {
        float a = lsum[s], c = amsum[s];
#pragma unroll
        for (int o = 16; o > 0; o >>= 1) {
            a += __shfl_xor_sync(~0u, a, o);
            c += __shfl_xor_sync(~0u, c, o);
        }
        lsum[s] = a; amsum[s] = c;
    }
    const int pidx = b * NW + w;
#pragma unroll
    for (int s = 0; s < SS; s++)
        ((float4*)g_pax)[(pidx * SS + s) * 32 + lane] = acc[s];
    if (lane == 0) {
#pragma unroll
        for (int s = 0; s < SS; s++) {
            g_pm[pidx * SS + s] = m[s];
            g_pl[pidx * SS + s] = lsum[s];
            g_pam[pidx * SS + s] = amsum[s];
        }
    }
}

// ---------------- combine + updates + GRU + FF + next-q ------------------
__global__ void __launch_bounds__(128)
k_up(const float* __restrict__ bvv,
     const float* __restrict__ bih, const float* __restrict__ bhh,
     const float* __restrict__ b1, const float* __restrict__ b2,
     const float* __restrict__ lfg, const float* __restrict__ lfb,
     const float* __restrict__ bq, const float* __restrict__ Wk,
     const float* __restrict__ lsg, const float* __restrict__ lsb,
     const float* __restrict__ ling, const float* __restrict__ linb,
     float* __restrict__ out, int last) {
    const int b = blockIdx.x / SS;
    const int s = blockIdx.x % SS;
    const int d = threadIdx.x;
    const int w = d >> 5, ln = d & 31;

    __shared__ float su[DD], sx[DD], shh[DD], lnv[DD], sf[HH], sw[NW];
    __shared__ float red[8];

    // ---- A: merge flash partials (x-space) ----
    float pmv = -INFINITY, plv = 0.f, pamv = 0.f;
    if (d < NW) {
        pmv = g_pm[(b * NW + d) * SS + s];
        plv = g_pl[(b * NW + d) * SS + s];
        pamv = g_pam[(b * NW + d) * SS + s];
    }
    float mm = pmv;
#pragma unroll
    for (int o = 16; o > 0; o >>= 1) mm = fmaxf(mm, __shfl_xor_sync(~0u, mm, o));
    if (ln == 0) red[w] = mm;
    __syncthreads();
    float M = fmaxf(fmaxf(red[0], red[1]), fmaxf(red[2], red[3]));
    float wgt = (d < NW) ? __expf(pmv - M) : 0.f;
    if (d < NW) sw[d] = wgt;
    float lw = plv * wgt, aw = pamv * wgt;
#pragma unroll
    for (int o = 16; o > 0; o >>= 1) {
        lw += __shfl_xor_sync(~0u, lw, o);
        aw += __shfl_xor_sync(~0u, aw, o);
    }
    __syncthreads();
    if (ln == 0) { red[w] = lw; red[4 + w] = aw; }
    __syncthreads();
    float L = red[0] + red[1] + red[2] + red[3];
    float AM = red[4] + red[5] + red[6] + red[7];

    float AX = 0.f;
    const float* pa = g_pax + ((long long)(b * NW) * SS + s) * DD + d;
#pragma unroll 4
    for (int sp = 0; sp < NW; sp++)
        AX = fmaf(pa[sp * SS * DD], sw[sp], AX);
    const float invC = 1.f / (1.f + (float)NN * EPSV);
    float accv = ling[d] * (AX - AM) + linb[d] * L;
    su[d] = (accv / L + EPSV * g_es[b * DD + d]) * invC;
    float h = g_slots[(b * SS + s) * DD + d];
    shh[d] = h;
    __syncthreads();

    // ---- B: updates = u @ Wv^T + bv ----
    float xv = bvv[d];
#pragma unroll 8
    for (int e = 0; e < DD; e++) xv = fmaf(su[e], g_WvT[e * DD + d], xv);
    sx[d] = xv;
    __syncthreads();

    // ---- C: GRU (r,z,n) ----
    float gir = bih[d], giz = bih[DD + d], gin = bih[2 * DD + d];
    float ghr = bhh[d], ghz = bhh[DD + d], ghn = bhh[2 * DD + d];
#pragma unroll 4
    for (int e = 0; e < DD; e++) {
        float xe = sx[e], he = shh[e];
        const float* wi = g_WihT + e * 3 * DD + d;
        const float* wh = g_WhhT + e * 3 * DD + d;
        gir = fmaf(xe, wi[0], gir);
        giz = fmaf(xe, wi[DD], giz);
        gin = fmaf(xe, wi[2 * DD], gin);
        ghr = fmaf(he, wh[0], ghr);
        ghz = fmaf(he, wh[DD], ghz);
        ghn = fmaf(he, wh[2 * DD], ghn);
    }
    float r = 1.f / (1.f + expf(-(gir + ghr)));
    float z = 1.f / (1.f + expf(-(giz + ghz)));
    float n = tanhf(fmaf(r, ghn, gin));
    float sv = fmaf(z, h - n, n);

    // ---- D: LN_ff ----
    {
        float a = sv, c = sv * sv;
#pragma unroll
        for (int o = 16; o > 0; o >>= 1) {
            a += __shfl_xor_sync(~0u, a, o);
            c += __shfl_xor_sync(~0u, c, o);
        }
        __syncthreads();
        if (ln == 0) { red[w] = a; red[4 + w] = c; }
        __syncthreads();
        float mean = (red[0] + red[1] + red[2] + red[3]) * (1.f / DD);
        float msq = (red[4] + red[5] + red[6] + red[7]) * (1.f / DD);
        float rstd = rsqrtf(msq - mean * mean + 1e-5f);
        lnv[d] = fmaf((sv - mean) * rstd, lfg[d], lfb[d]);
    }
    __syncthreads();

    // ---- E: FF1 (relu) ----
    float f1 = b1[d], f2 = b1[DD + d];
#pragma unroll 8
    for (int e = 0; e < DD; e++) {
        float le = lnv[e];
        f1 = fmaf(le, g_W1T[e * HH + d], f1);
        f2 = fmaf(le, g_W1T[e * HH + DD + d], f2);
    }
    sf[d] = fmaxf(f1, 0.f);
    sf[DD + d] = fmaxf(f2, 0.f);
    __syncthreads();

    // ---- F: FF2 + residual ----
    float o2 = b2[d];
#pragma unroll 8
    for (int hh = 0; hh < HH; hh++) o2 = fmaf(sf[hh], g_W2T[hh * DD + d], o2);
    float res = sv + o2;
    g_slots[(b * SS + s) * DD + d] = res;
    if (last) {
        out[(b * SS + s) * DD + d] = res;
    } else {
        // ---- G: q projection for next iteration (+ wq/ws/c1) ----
        float a = res, c = res * res;
#pragma unroll
        for (int o = 16; o > 0; o >>= 1) {
            a += __shfl_xor_sync(~0u, a, o);
            c += __shfl_xor_sync(~0u, c, o);
        }
        __syncthreads();
        if (ln == 0) { red[w] = a; red[4 + w] = c; }
        __syncthreads();
        float mean = (red[0] + red[1] + red[2] + red[3]) * (1.f / DD);
        float msq = (red[4] + red[5] + red[6] + red[7]) * (1.f / DD);
        float rstd = rsqrtf(msq - mean * mean + 1e-5f);
        su[d] = fmaf((res - mean) * rstd, lsg[d], lsb[d]);
        __syncthreads();
        float q = bq[d];
#pragma unroll 8
        for (int e = 0; e < DD; e++) q = fmaf(su[e], g_WqT[e * DD + d], q);
        sx[d] = q;
        __syncthreads();
        float qt = 0.f;
#pragma unroll 8
        for (int e = 0; e < DD; e++) qt = fmaf(sx[e], Wk[e * DD + d], qt);
        float wqv = qt * ling[d];
        float c1v = qt * linb[d];
        g_wq[(b * SS + s) * DD + d] = wqv;
        float aa = wqv, cc = c1v;
#pragma unroll
        for (int o = 16; o > 0; o >>= 1) {
            aa += __shfl_xor_sync(~0u, aa, o);
            cc += __shfl_xor_sync(~0u, cc, o);
        }
        __syncthreads();
        if (ln == 0) { red[w] = aa; red[4 + w] = cc; }
        __syncthreads();
        if (d == 0) {
            g_ws[b * SS + s] = red[0] + red[1] + red[2] + red[3];
            g_c1[b * SS + s] = red[4] + red[5] + red[6] + red[7];
        }
    }
}

// ---------------- launch ----------------
extern "C" void kernel_launch(void* const* d_in, const int* in_sizes, int n_in,
                              void* d_out, int out_size) {
    (void)in_sizes; (void)n_in; (void)out_size;
    const float* emb   = (const float*)d_in[0];
    const float* noise = (const float*)d_in[1];
    const float* mu    = (const float*)d_in[2];
    const float* sg    = (const float*)d_in[3];
    const float* Wk    = (const float*)d_in[4];
    /* bk = d_in[5] unused: constant per-(b,s) logit shift cancels in softmax */
    const float* Wq    = (const float*)d_in[6];
    const float* bq    = (const float*)d_in[7];
    const float* Wv    = (const float*)d_in[8];
    const float* bvv   = (const float*)d_in[9];
    const float* Wih   = (const float*)d_in[10];
    const float* Whh   = (const float*)d_in[11];
    const float* bih   = (const float*)d_in[12];
    const float* bhh   = (const float*)d_in[13];
    const float* W1    = (const float*)d_in[14];
    const float* b1    = (const float*)d_in[15];
    const float* W2    = (const float*)d_in[16];
    const float* b2    = (const float*)d_in[17];
    const float* lin_g = (const float*)d_in[18];
    const float* lin_b = (const float*)d_in[19];
    const float* ls_g  = (const float*)d_in[20];
    const float* ls_b  = (const float*)d_in[21];
    const float* lf_g  = (const float*)d_in[22];
    const float* lf_b  = (const float*)d_in[23];
    float* out = (float*)d_out;

    k_init<<<(BB * SS * DD + 255) / 256, 256>>>(noise, mu, sg);
    k_tr_all<<<192, dim3(32, 8)>>>(Wq, Wv, Wih, Whh, W1, W2);
    k_prep<<<dim3(8, BB), 256>>>(emb);
    k_es<<<BB, DD>>>(lin_g, lin_b);
    k_q0<<<BB * SS, DD>>>(bq, Wk, ls_g, ls_b, lin_g, lin_b);
    for (int it = 0; it < 3; it++) {
        k_flash<<<dim3(NW, BB), 32>>>(emb);
        k_up<<<BB * SS, DD>>>(bvv, bih, bhh, b1, b2, lf_g, lf_b,
                              bq, Wk, ls_g, ls_b, lin_g, lin_b, out, it == 2);
    }
}

// round 10
// speedup vs baseline: 4.8728x; 1.5860x over previous
#include <cuda_runtime.h>
#include <math.h>

#define BB 64
#define NN 4096
#define DD 128
#define SS 7
#define HH 256
#define NW 64                    // warp-partials per batch
#define RPW 64                   // rows per warp
#define EPSV 1e-8f

// ---------------- device scratch ----------------
__device__ __align__(16) float g_slots[BB * SS * DD];
__device__ __align__(16) float g_wq[BB * SS * DD];     // qt ∘ lin_g
__device__ float g_ws[BB * SS];                        // Σ (qt∘lin_g)
__device__ float g_c1[BB * SS];                        // qt · lin_b
__device__ __align__(16) float g_mv[BB * NN * 2];      // per-row (mean, rstd)
__device__ __align__(16) float g_es[BB * DD];          // per-batch Σ e_ln
__device__ __align__(16) float g_pesx[BB * NW * DD];
__device__ float g_pesm[BB * NW];
__device__ float g_pm[BB * NW * SS];
__device__ float g_pl[BB * NW * SS];
__device__ float g_pam[BB * NW * SS];
__device__ __align__(16) float g_pax[BB * NW * SS * DD];
// transposed weights: WT[in * O + out]
__device__ __align__(16) float g_WqT[DD * DD];
__device__ __align__(16) float g_WvT[DD * DD];
__device__ __align__(16) float g_WihT[DD * 3 * DD];
__device__ __align__(16) float g_WhhT[DD * 3 * DD];
__device__ __align__(16) float g_W1T[DD * HH];
__device__ __align__(16) float g_W2T[HH * DD];

// ---------------- fused: transpose all weights (blocks 0..191) + slot init
__global__ void k_trinit(const float* __restrict__ Wq, const float* __restrict__ Wv,
                         const float* __restrict__ Wih, const float* __restrict__ Whh,
                         const float* __restrict__ W1, const float* __restrict__ W2,
                         const float* __restrict__ noise, const float* __restrict__ mu,
                         const float* __restrict__ sg) {
    int id = blockIdx.x;
    if (id >= 192) {
        int i = (id - 192) * 256 + threadIdx.x;   // exactly BB*SS*DD = 224*256
        int dd = i & (DD - 1);
        g_slots[i] = fmaf(sg[dd], noise[i], mu[dd]);
        return;
    }
    const float* src; float* dst; int O, I, ti, to;
    if (id < 16)       { src = Wq;  dst = g_WqT;  O = DD;     I = DD; ti = id & 3; to = id >> 2; }
    else if (id < 32)  { id -= 16;  src = Wv;  dst = g_WvT;  O = DD;     I = DD; ti = id & 3; to = id >> 2; }
    else if (id < 80)  { id -= 32;  src = Wih; dst = g_WihT; O = 3 * DD; I = DD; ti = id & 3; to = id >> 2; }
    else if (id < 128) { id -= 80;  src = Whh; dst = g_WhhT; O = 3 * DD; I = DD; ti = id & 3; to = id >> 2; }
    else if (id < 160) { id -= 128; src = W1;  dst = g_W1T;  O = HH;     I = DD; ti = id & 3; to = id >> 2; }
    else               { id -= 160; src = W2;  dst = g_W2T;  O = DD;     I = HH; ti = id & 7; to = id >> 3; }
    __shared__ float tile[32][33];
    int tx = threadIdx.x & 31, ty = threadIdx.x >> 5;
    int i0 = ti * 32, o0 = to * 32;
#pragma unroll
    for (int k = 0; k < 32; k += 8)
        tile[ty + k][tx] = src[(o0 + ty + k) * I + i0 + tx];
    __syncthreads();
#pragma unroll
    for (int k = 0; k < 32; k += 8)
        dst[(i0 + ty + k) * O + o0 + tx] = tile[tx][ty + k];
}

// ---------------- prep: per-row LN stats + es partials (once) ------------
__global__ void __launch_bounds__(256) k_prep(const float* __restrict__ emb) {
    const int lane = threadIdx.x & 31, wid = threadIdx.x >> 5;
    const int b = blockIdx.y, w = blockIdx.x * 8 + wid;
    const float4* base = (const float4*)emb + (long long)(b * NN + w * RPW) * 32 + lane;
    float2* mvout = (float2*)g_mv + (b * NN + w * RPW);
    float4 esx = make_float4(0.f, 0.f, 0.f, 0.f);
    float esm = 0.f;
    for (int r = 0; r < RPW; r++) {
        float4 x = base[r * 32];
        float s1 = x.x + x.y + x.z + x.w;
        float s2 = fmaf(x.x, x.x, fmaf(x.y, x.y, fmaf(x.z, x.z, x.w * x.w)));
#pragma unroll
        for (int o = 16; o > 0; o >>= 1) {
            s1 += __shfl_xor_sync(~0u, s1, o);
            s2 += __shfl_xor_sync(~0u, s2, o);
        }
        float mean = s1 * (1.f / DD);
        float rstd = rsqrtf(fmaf(-mean, mean, s2 * (1.f / DD)) + 1e-5f);
        if (lane == 0) mvout[r] = make_float2(mean, rstd);
        esx.x = fmaf(rstd, x.x, esx.x);
        esx.y = fmaf(rstd, x.y, esx.y);
        esx.z = fmaf(rstd, x.z, esx.z);
        esx.w = fmaf(rstd, x.w, esx.w);
        esm = fmaf(rstd, mean, esm);
    }
    ((float4*)g_pesx)[(b * NW + w) * 32 + lane] = esx;
    if (lane == 0) g_pesm[b * NW + w] = esm;
}

// ---------------- es finalize ----------------
__global__ void k_es(const float* __restrict__ lg, const float* __restrict__ lb) {
    int b = blockIdx.x, d = threadIdx.x;
    float s0 = 0.f, s1 = 0.f, m0 = 0.f, m1 = 0.f;
#pragma unroll 8
    for (int w = 0; w < NW; w += 2) {
        s0 += g_pesx[(b * NW + w) * DD + d];
        s1 += g_pesx[(b * NW + w + 1) * DD + d];
        m0 += g_pesm[b * NW + w];
        m1 += g_pesm[b * NW + w + 1];
    }
    g_es[b * DD + d] = lg[d] * ((s0 + s1) - (m0 + m1)) + (float)NN * lb[d];
}

// ---------------- initial q projection (iter 0) --------------------------
__global__ void __launch_bounds__(128)
k_q0(const float* __restrict__ bq, const float* __restrict__ Wk,
     const float* __restrict__ lg, const float* __restrict__ lb,
     const float* __restrict__ ling, const float* __restrict__ linb) {
    const int bs = blockIdx.x;
    const int d = threadIdx.x;
    const int w = d >> 5, ln = d & 31;
    __shared__ float lnq[DD], sq[DD], red[8];

    float x = g_slots[bs * DD + d];
    float a = x, c = x * x;
#pragma unroll
    for (int o = 16; o > 0; o >>= 1) {
        a += __shfl_xor_sync(~0u, a, o);
        c += __shfl_xor_sync(~0u, c, o);
    }
    if (ln == 0) { red[w] = a; red[4 + w] = c; }
    __syncthreads();
    float mean = (red[0] + red[1] + red[2] + red[3]) * (1.f / DD);
    float msq = (red[4] + red[5] + red[6] + red[7]) * (1.f / DD);
    float rstd = rsqrtf(msq - mean * mean + 1e-5f);
    lnq[d] = fmaf((x - mean) * rstd, lg[d], lb[d]);
    __syncthreads();

    float q = bq[d];
#pragma unroll 8
    for (int e = 0; e < DD; e++) q = fmaf(lnq[e], g_WqT[e * DD + d], q);
    sq[d] = q;
    __syncthreads();
    float qt = 0.f;
#pragma unroll 8
    for (int e = 0; e < DD; e++) qt = fmaf(sq[e], Wk[e * DD + d], qt);

    float wqv = qt * ling[d];
    float c1v = qt * linb[d];
    g_wq[bs * DD + d] = wqv;
    float aa = wqv, cc = c1v;
#pragma unroll
    for (int o = 16; o > 0; o >>= 1) {
        aa += __shfl_xor_sync(~0u, aa, o);
        cc += __shfl_xor_sync(~0u, cc, o);
    }
    __syncthreads();
    if (ln == 0) { red[w] = aa; red[4 + w] = cc; }
    __syncthreads();
    if (d == 0) {
        g_ws[bs] = red[0] + red[1] + red[2] + red[3];
        g_c1[bs] = red[4] + red[5] + red[6] + red[7];
    }
}

// ---------------- flash: lane-per-row logits, x-space accumulation -------
__global__ void __launch_bounds__(32)
k_flash(const float* __restrict__ emb) {
    __shared__ float4 xt[32][33];       // 32 rows x 128 floats, padded
    __shared__ float4 wqs[SS][32];      // wq vectors
    __shared__ float ps[32][12];        // per-row probs*rstd (7 + pad)
    const int lane = threadIdx.x;
    const int b = blockIdx.y, w = blockIdx.x;

#pragma unroll
    for (int s = 0; s < SS; s++)
        wqs[s][lane] = ((const float4*)g_wq)[(b * SS + s) * 32 + lane];
    float ws[SS], c1[SS];
#pragma unroll
    for (int s = 0; s < SS; s++) {
        ws[s] = g_ws[b * SS + s];
        c1[s] = g_c1[b * SS + s];
    }

    float m[SS], lsum[SS], amsum[SS];
    float4 acc[SS];
#pragma unroll
    for (int s = 0; s < SS; s++) {
        m[s] = -INFINITY; lsum[s] = 0.f; amsum[s] = 0.f;
        acc[s] = make_float4(0.f, 0.f, 0.f, 0.f);
    }
    const float4* gbase = (const float4*)emb + (long long)(b * NN + w * RPW) * 32;
    const float2* mvb = (const float2*)g_mv + (b * NN + w * RPW);
    __syncwarp();

    for (int t = 0; t < RPW / 32; t++) {
#pragma unroll 8
        for (int k = 0; k < 32; k++)
            xt[k][lane] = gbase[(t * 32 + k) * 32 + lane];
        float2 mv = mvb[t * 32 + lane];
        __syncwarp();

        float z[SS];
#pragma unroll
        for (int s = 0; s < SS; s++) z[s] = 0.f;
#pragma unroll 4
        for (int e = 0; e < 32; e++) {
            float4 xv = xt[lane][e];
#pragma unroll
            for (int s = 0; s < SS; s++) {
                float4 wv = wqs[s][e];
                z[s] = fmaf(xv.x, wv.x, fmaf(xv.y, wv.y,
                       fmaf(xv.z, wv.z, fmaf(xv.w, wv.w, z[s]))));
            }
        }
#pragma unroll
        for (int s = 0; s < SS; s++)
            z[s] = fmaf(mv.y, fmaf(-mv.x, ws[s], z[s]), c1[s]);

#pragma unroll
        for (int s = 0; s < SS; s++) {
            float zm = z[s];
#pragma unroll
            for (int o = 16; o > 0; o >>= 1)
                zm = fmaxf(zm, __shfl_xor_sync(~0u, zm, o));
            if (zm > m[s]) {
                float sc = __expf(m[s] - zm);
                m[s] = zm;
                lsum[s] *= sc;
                amsum[s] *= sc;
                acc[s].x *= sc; acc[s].y *= sc; acc[s].z *= sc; acc[s].w *= sc;
            }
        }
        float pr[SS];
#pragma unroll
        for (int s = 0; s < SS; s++) {
            float pv = __expf(z[s] - m[s]);
            lsum[s] += pv;
            pr[s] = pv * mv.y;
            amsum[s] = fmaf(pr[s], mv.x, amsum[s]);
        }
        *(float4*)&ps[lane][0] = make_float4(pr[0], pr[1], pr[2], pr[3]);
        *(float4*)&ps[lane][4] = make_float4(pr[4], pr[5], pr[6], 0.f);
        __syncwarp();

#pragma unroll 4
        for (int r = 0; r < 32; r++) {
            float4 xv = xt[r][lane];
            float4 pa = *(const float4*)&ps[r][0];
            float4 pb = *(const float4*)&ps[r][4];
            float prv[SS] = {pa.x, pa.y, pa.z, pa.w, pb.x, pb.y, pb.z};
#pragma unroll
            for (int s = 0; s < SS; s++) {
                acc[s].x = fmaf(prv[s], xv.x, acc[s].x);
                acc[s].y = fmaf(prv[s], xv.y, acc[s].y);
                acc[s].z = fmaf(prv[s], xv.z, acc[s].z);
                acc[s].w = fmaf(prv[s], xv.w, acc[s].w);
            }
        }
        __syncwarp();
    }

#pragma unroll
    for (int s = 0; s < SS; s++) {
        float a = lsum[s], c = amsum[s];
#pragma unroll
        for (int o = 16; o > 0; o >>= 1) {
            a += __shfl_xor_sync(~0u, a, o);
            c += __shfl_xor_sync(~0u, c, o);
        }
        lsum[s] = a; amsum[s] = c;
    }
    const int pidx = b * NW + w;
#pragma unroll
    for (int s = 0; s < SS; s++)
        ((float4*)g_pax)[(pidx * SS + s) * 32 + lane] = acc[s];
    if (lane == 0) {
#pragma unroll
        for (int s = 0; s < SS; s++) {
            g_pm[pidx * SS + s] = m[s];
            g_pl[pidx * SS + s] = lsum[s];
            g_pam[pidx * SS + s] = amsum[s];
        }
    }
}

// ---------------- combine + updates + GRU + FF + next-q ------------------
// one block per (b,s) row, 256 threads: thread = (d = t&127, h = t>>7 half of e)
__global__ void __launch_bounds__(256)
k_up(const float* __restrict__ bvv,
     const float* __restrict__ bih, const float* __restrict__ bhh,
     const float* __restrict__ b1, const float* __restrict__ b2,
     const float* __restrict__ lfg, const float* __restrict__ lfb,
     const float* __restrict__ bq, const float* __restrict__ Wk,
     const float* __restrict__ lsg, const float* __restrict__ lsb,
     const float* __restrict__ ling, const float* __restrict__ linb,
     float* __restrict__ out, int last) {
    const int b = blockIdx.x / SS;
    const int s = blockIdx.x % SS;
    const int t = threadIdx.x;      // 0..255
    const int d = t & 127;
    const int h = t >> 7;           // e-half
    const int w = t >> 5, ln = t & 31;
    const int e0 = h * 64;

    __shared__ float su[DD], sx[DD], shh[DD], lnv[DD], sf[HH], sw[NW];
    __shared__ float sp2[2][DD];
    __shared__ float sg6[2][6][DD];
    __shared__ float red[8], red2[8];

    float hval = g_slots[(b * SS + s) * DD + d];

    // ---- A: merge flash partials ----
    float pmv = -INFINITY, plv = 0.f, pamv = 0.f;
    if (t < NW) {
        pmv = g_pm[(b * NW + t) * SS + s];
        plv = g_pl[(b * NW + t) * SS + s];
        pamv = g_pam[(b * NW + t) * SS + s];
    }
    float mm = pmv;
#pragma unroll
    for (int o = 16; o > 0; o >>= 1) mm = fmaxf(mm, __shfl_xor_sync(~0u, mm, o));
    if (ln == 0) red[w] = mm;
    __syncthreads();
    float M = -INFINITY;
#pragma unroll
    for (int i = 0; i < 8; i++) M = fmaxf(M, red[i]);
    float wgt = (t < NW) ? __expf(pmv - M) : 0.f;
    if (t < NW) sw[t] = wgt;
    float lw = plv * wgt, aw = pamv * wgt;
#pragma unroll
    for (int o = 16; o > 0; o >>= 1) {
        lw += __shfl_xor_sync(~0u, lw, o);
        aw += __shfl_xor_sync(~0u, aw, o);
    }
    __syncthreads();
    if (ln == 0) { red[w] = lw; red2[w] = aw; }
    __syncthreads();
    float L = 0.f, AM = 0.f;
#pragma unroll
    for (int i = 0; i < 8; i++) { L += red[i]; AM += red2[i]; }

    // AX partial over this thread's 32 source warps
    {
        float a0 = 0.f, a1 = 0.f;
        const float* pa = g_pax + ((long long)(b * NW + h * 32) * SS + s) * DD + d;
        const float* swp = sw + h * 32;
#pragma unroll 4
        for (int sp = 0; sp < 32; sp += 2) {
            a0 = fmaf(pa[sp * SS * DD], swp[sp], a0);
            a1 = fmaf(pa[(sp + 1) * SS * DD], swp[sp + 1], a1);
        }
        sp2[h][d] = a0 + a1;
    }
    __syncthreads();
    const float invC = 1.f / (1.f + (float)NN * EPSV);
    if (h == 0) {
        float AX = sp2[0][d] + sp2[1][d];
        float accv = ling[d] * (AX - AM) + linb[d] * L;
        su[d] = (accv / L + EPSV * g_es[b * DD + d]) * invC;
        shh[d] = hval;
    }
    __syncthreads();

    // ---- B: updates = u @ Wv^T + bv (e-split) ----
    {
        float x0 = 0.f, x1 = 0.f;
#pragma unroll 8
        for (int i = 0; i < 64; i += 2) {
            int e = e0 + i;
            x0 = fmaf(su[e], g_WvT[e * DD + d], x0);
            x1 = fmaf(su[e + 1], g_WvT[(e + 1) * DD + d], x1);
        }
        sp2[h][d] = x0 + x1;
    }
    __syncthreads();
    if (h == 0) sx[d] = bvv[d] + sp2[0][d] + sp2[1][d];
    __syncthreads();

    // ---- C: GRU partials (e-split, 6 independent accumulators) ----
    {
        float gir = 0.f, giz = 0.f, gin = 0.f, ghr = 0.f, ghz = 0.f, ghn = 0.f;
#pragma unroll 4
        for (int i = 0; i < 64; i++) {
            int e = e0 + i;
            float xe = sx[e], he = shh[e];
            const float* wi = g_WihT + e * 3 * DD + d;
            const float* wh = g_WhhT + e * 3 * DD + d;
            gir = fmaf(xe, wi[0], gir);
            giz = fmaf(xe, wi[DD], giz);
            gin = fmaf(xe, wi[2 * DD], gin);
            ghr = fmaf(he, wh[0], ghr);
            ghz = fmaf(he, wh[DD], ghz);
            ghn = fmaf(he, wh[2 * DD], ghn);
        }
        sg6[h][0][d] = gir; sg6[h][1][d] = giz; sg6[h][2][d] = gin;
        sg6[h][3][d] = ghr; sg6[h][4][d] = ghz; sg6[h][5][d] = ghn;
    }
    __syncthreads();
    float sv = 0.f;
    if (h == 0) {
        float gir = bih[d] + sg6[0][0][d] + sg6[1][0][d];
        float giz = bih[DD + d] + sg6[0][1][d] + sg6[1][1][d];
        float gin = bih[2 * DD + d] + sg6[0][2][d] + sg6[1][2][d];
        float ghr = bhh[d] + sg6[0][3][d] + sg6[1][3][d];
        float ghz = bhh[DD + d] + sg6[0][4][d] + sg6[1][4][d];
        float ghn = bhh[2 * DD + d] + sg6[0][5][d] + sg6[1][5][d];
        float r = 1.f / (1.f + expf(-(gir + ghr)));
        float z = 1.f / (1.f + expf(-(giz + ghz)));
        float n = tanhf(fmaf(r, ghn, gin));
        sv = fmaf(z, hval - n, n);
    }

    // ---- D: LN_ff (block reduce over 128 values) ----
    {
        float a = sv, c = sv * sv;   // zero for h==1
#pragma unroll
        for (int o = 16; o > 0; o >>= 1) {
            a += __shfl_xor_sync(~0u, a, o);
            c += __shfl_xor_sync(~0u, c, o);
        }
        __syncthreads();
        if (ln == 0) { red[w] = a; red2[w] = c; }
        __syncthreads();
        float sa = 0.f, sc = 0.f;
#pragma unroll
        for (int i = 0; i < 8; i++) { sa += red[i]; sc += red2[i]; }
        float mean = sa * (1.f / DD);
        float msq = sc * (1.f / DD);
        float rstd = rsqrtf(msq - mean * mean + 1e-5f);
        if (h == 0) lnv[d] = fmaf((sv - mean) * rstd, lfg[d], lfb[d]);
    }
    __syncthreads();

    // ---- E: FF1 (relu), one output per thread (256 outputs) ----
    {
        float f0 = 0.f, f1 = 0.f;
#pragma unroll 8
        for (int e = 0; e < DD; e += 2) {
            f0 = fmaf(lnv[e], g_W1T[e * HH + t], f0);
            f1 = fmaf(lnv[e + 1], g_W1T[(e + 1) * HH + t], f1);
        }
        sf[t] = fmaxf(f0 + f1 + b1[t], 0.f);
    }
    __syncthreads();

    // ---- F: FF2 partial (h-split over 256 hidden) ----
    {
        float o0 = 0.f, o1 = 0.f;
        int hh0 = h * 128;
#pragma unroll 8
        for (int i = 0; i < 128; i += 2) {
            int hh = hh0 + i;
            o0 = fmaf(sf[hh], g_W2T[hh * DD + d], o0);
            o1 = fmaf(sf[hh + 1], g_W2T[(hh + 1) * DD + d], o1);
        }
        sp2[h][d] = o0 + o1;
    }
    __syncthreads();
    float res = 0.f;
    if (h == 0) {
        res = sv + b2[d] + sp2[0][d] + sp2[1][d];
        g_slots[(b * SS + s) * DD + d] = res;
        if (last) out[(b * SS + s) * DD + d] = res;
    }

    if (!last) {
        // ---- G1: LN_s over res ----
        float a = res, c = res * res;   // zero for h==1
#pragma unroll
        for (int o = 16; o > 0; o >>= 1) {
            a += __shfl_xor_sync(~0u, a, o);
            c += __shfl_xor_sync(~0u, c, o);
        }
        __syncthreads();
        if (ln == 0) { red[w] = a; red2[w] = c; }
        __syncthreads();
        float sa = 0.f, sc = 0.f;
#pragma unroll
        for (int i = 0; i < 8; i++) { sa += red[i]; sc += red2[i]; }
        float mean = sa * (1.f / DD);
        float msq = sc * (1.f / DD);
        float rstd = rsqrtf(msq - mean * mean + 1e-5f);
        if (h == 0) su[d] = fmaf((res - mean) * rstd, lsg[d], lsb[d]);
        __syncthreads();

        // ---- G2: q = LN_s @ WqT + bq (e-split) ----
        {
            float q0 = 0.f, q1 = 0.f;
#pragma unroll 8
            for (int i = 0; i < 64; i += 2) {
                int e = e0 + i;
                q0 = fmaf(su[e], g_WqT[e * DD + d], q0);
                q1 = fmaf(su[e + 1], g_WqT[(e + 1) * DD + d], q1);
            }
            sp2[h][d] = q0 + q1;
        }
        __syncthreads();
        if (h == 0) sx[d] = bq[d] + sp2[0][d] + sp2[1][d];
        __syncthreads();

        // ---- G3: qt = q @ Wk (e-split) ----
        {
            float q0 = 0.f, q1 = 0.f;
#pragma unroll 8
            for (int i = 0; i < 64; i += 2) {
                int e = e0 + i;
                q0 = fmaf(sx[e], Wk[e * DD + d], q0);
                q1 = fmaf(sx[e + 1], Wk[(e + 1) * DD + d], q1);
            }
            sp2[h][d] = q0 + q1;
        }
        __syncthreads();
        float wqv = 0.f, c1v = 0.f;
        if (h == 0) {
            float qt = sp2[0][d] + sp2[1][d];
            wqv = qt * ling[d];
            c1v = qt * linb[d];
            g_wq[(b * SS + s) * DD + d] = wqv;
        }
        float aa = wqv, cc = c1v;
#pragma unroll
        for (int o = 16; o > 0; o >>= 1) {
            aa += __shfl_xor_sync(~0u, aa, o);
            cc += __shfl_xor_sync(~0u, cc, o);
        }
        __syncthreads();
        if (ln == 0) { red[w] = aa; red2[w] = cc; }
        __syncthreads();
        if (t == 0) {
            float sws = 0.f, sc1 = 0.f;
#pragma unroll
            for (int i = 0; i < 8; i++) { sws += red[i]; sc1 += red2[i]; }
            g_ws[b * SS + s] = sws;
            g_c1[b * SS + s] = sc1;
        }
    }
}

// ---------------- launch ----------------
extern "C" void kernel_launch(void* const* d_in, const int* in_sizes, int n_in,
                              void* d_out, int out_size) {
    (void)in_sizes; (void)n_in; (void)out_size;
    const float* emb   = (const float*)d_in[0];
    const float* noise = (const float*)d_in[1];
    const float* mu    = (const float*)d_in[2];
    const float* sg    = (const float*)d_in[3];
    const float* Wk    = (const float*)d_in[4];
    /* bk = d_in[5] unused: constant per-(b,s) logit shift cancels in softmax */
    const float* Wq    = (const float*)d_in[6];
    const float* bq    = (const float*)d_in[7];
    const float* Wv    = (const float*)d_in[8];
    const float* bvv   = (const float*)d_in[9];
    const float* Wih   = (const float*)d_in[10];
    const float* Whh   = (const float*)d_in[11];
    const float* bih   = (const float*)d_in[12];
    const float* bhh   = (const float*)d_in[13];
    const float* W1    = (const float*)d_in[14];
    const float* b1    = (const float*)d_in[15];
    const float* W2    = (const float*)d_in[16];
    const float* b2    = (const float*)d_in[17];
    const float* lin_g = (const float*)d_in[18];
    const float* lin_b = (const float*)d_in[19];
    const float* ls_g  = (const float*)d_in[20];
    const float* ls_b  = (const float*)d_in[21];
    const float* lf_g  = (const float*)d_in[22];
    const float* lf_b  = (const float*)d_in[23];
    float* out = (float*)d_out;

    k_trinit<<<416, 256>>>(Wq, Wv, Wih, Whh, W1, W2, noise, mu, sg);   // #1
    k_prep<<<dim3(8, BB), 256>>>(emb);                                  // #2
    k_q0<<<BB * SS, DD>>>(bq, Wk, ls_g, ls_b, lin_g, lin_b);            // #3
    for (int it = 0; it < 3; it++) {
        k_flash<<<dim3(NW, BB), 32>>>(emb);                             // #4 on it==0
        if (it == 0) k_es<<<BB, DD>>>(lin_g, lin_b);                    // #5
        k_up<<<BB * SS, 256>>>(bvv, bih, bhh, b1, b2, lf_g, lf_b,
                               bq, Wk, ls_g, ls_b, lin_g, lin_b, out, it == 2);
    }
}

// round 11
// speedup vs baseline: 6.1579x; 1.2637x over previous
#include <cuda_runtime.h>
#include <math.h>

#define BB 64
#define NN 4096
#define DD 128
#define SS 7
#define HH 256
#define NW 64                    // warp-partials per batch
#define RPW 64                   // rows per flash block
#define EPSV 1e-8f

// ---------------- device scratch ----------------
__device__ __align__(16) float g_slots[BB * SS * DD];
__device__ __align__(16) float g_wq[BB * SS * DD];     // qt ∘ lin_g
__device__ float g_ws[BB * SS];                        // Σ (qt∘lin_g)
__device__ float g_c1[BB * SS];                        // qt · lin_b
__device__ __align__(16) float g_mv[BB * NN * 2];      // per-row (mean, rstd)
__device__ __align__(16) float g_es[BB * DD];          // per-batch Σ e_ln
__device__ __align__(16) float g_pesx[BB * NW * DD];
__device__ float g_pesm[BB * NW];
__device__ float g_pm[BB * NW * SS];
__device__ float g_pl[BB * NW * SS];
__device__ float g_pam[BB * NW * SS];
__device__ __align__(16) float g_pax[BB * NW * SS * DD];
// transposed weights: WT[in * O + out]
__device__ __align__(16) float g_WqT[DD * DD];
__device__ __align__(16) float g_WvT[DD * DD];
__device__ __align__(16) float g_WihT[DD * 3 * DD];
__device__ __align__(16) float g_WhhT[DD * 3 * DD];
__device__ __align__(16) float g_W1T[DD * HH];
__device__ __align__(16) float g_W2T[HH * DD];

// ---------------- fused: transpose all weights (blocks 0..191) + slot init
__global__ void k_trinit(const float* __restrict__ Wq, const float* __restrict__ Wv,
                         const float* __restrict__ Wih, const float* __restrict__ Whh,
                         const float* __restrict__ W1, const float* __restrict__ W2,
                         const float* __restrict__ noise, const float* __restrict__ mu,
                         const float* __restrict__ sg) {
    int id = blockIdx.x;
    if (id >= 192) {
        int i = (id - 192) * 256 + threadIdx.x;   // exactly BB*SS*DD = 224*256
        int dd = i & (DD - 1);
        g_slots[i] = fmaf(sg[dd], noise[i], mu[dd]);
        return;
    }
    const float* src; float* dst; int O, I, ti, to;
    if (id < 16)       { src = Wq;  dst = g_WqT;  O = DD;     I = DD; ti = id & 3; to = id >> 2; }
    else if (id < 32)  { id -= 16;  src = Wv;  dst = g_WvT;  O = DD;     I = DD; ti = id & 3; to = id >> 2; }
    else if (id < 80)  { id -= 32;  src = Wih; dst = g_WihT; O = 3 * DD; I = DD; ti = id & 3; to = id >> 2; }
    else if (id < 128) { id -= 80;  src = Whh; dst = g_WhhT; O = 3 * DD; I = DD; ti = id & 3; to = id >> 2; }
    else if (id < 160) { id -= 128; src = W1;  dst = g_W1T;  O = HH;     I = DD; ti = id & 3; to = id >> 2; }
    else               { id -= 160; src = W2;  dst = g_W2T;  O = DD;     I = HH; ti = id & 7; to = id >> 3; }
    __shared__ float tile[32][33];
    int tx = threadIdx.x & 31, ty = threadIdx.x >> 5;
    int i0 = ti * 32, o0 = to * 32;
#pragma unroll
    for (int k = 0; k < 32; k += 8)
        tile[ty + k][tx] = src[(o0 + ty + k) * I + i0 + tx];
    __syncthreads();
#pragma unroll
    for (int k = 0; k < 32; k += 8)
        dst[(i0 + ty + k) * O + o0 + tx] = tile[tx][ty + k];
}

// ---------------- prep: per-row LN stats + es partials (once) ------------
__global__ void __launch_bounds__(256) k_prep(const float* __restrict__ emb) {
    const int lane = threadIdx.x & 31, wid = threadIdx.x >> 5;
    const int b = blockIdx.y, w = blockIdx.x * 8 + wid;
    const float4* base = (const float4*)emb + (long long)(b * NN + w * RPW) * 32 + lane;
    float2* mvout = (float2*)g_mv + (b * NN + w * RPW);
    float4 esx = make_float4(0.f, 0.f, 0.f, 0.f);
    float esm = 0.f;
    for (int r = 0; r < RPW; r++) {
        float4 x = base[r * 32];
        float s1 = x.x + x.y + x.z + x.w;
        float s2 = fmaf(x.x, x.x, fmaf(x.y, x.y, fmaf(x.z, x.z, x.w * x.w)));
#pragma unroll
        for (int o = 16; o > 0; o >>= 1) {
            s1 += __shfl_xor_sync(~0u, s1, o);
            s2 += __shfl_xor_sync(~0u, s2, o);
        }
        float mean = s1 * (1.f / DD);
        float rstd = rsqrtf(fmaf(-mean, mean, s2 * (1.f / DD)) + 1e-5f);
        if (lane == 0) mvout[r] = make_float2(mean, rstd);
        esx.x = fmaf(rstd, x.x, esx.x);
        esx.y = fmaf(rstd, x.y, esx.y);
        esx.z = fmaf(rstd, x.z, esx.z);
        esx.w = fmaf(rstd, x.w, esx.w);
        esm = fmaf(rstd, mean, esm);
    }
    ((float4*)g_pesx)[(b * NW + w) * 32 + lane] = esx;
    if (lane == 0) g_pesm[b * NW + w] = esm;
}

// ---------------- es finalize ----------------
__global__ void k_es(const float* __restrict__ lg, const float* __restrict__ lb) {
    int b = blockIdx.x, d = threadIdx.x;
    float s0 = 0.f, s1 = 0.f, m0 = 0.f, m1 = 0.f;
#pragma unroll 8
    for (int w = 0; w < NW; w += 2) {
        s0 += g_pesx[(b * NW + w) * DD + d];
        s1 += g_pesx[(b * NW + w + 1) * DD + d];
        m0 += g_pesm[b * NW + w];
        m1 += g_pesm[b * NW + w + 1];
    }
    g_es[b * DD + d] = lg[d] * ((s0 + s1) - (m0 + m1)) + (float)NN * lb[d];
}

// ---------------- initial q projection (iter 0) --------------------------
__global__ void __launch_bounds__(128)
k_q0(const float* __restrict__ bq, const float* __restrict__ Wk,
     const float* __restrict__ lg, const float* __restrict__ lb,
     const float* __restrict__ ling, const float* __restrict__ linb) {
    const int bs = blockIdx.x;
    const int d = threadIdx.x;
    const int w = d >> 5, ln = d & 31;
    __shared__ float lnq[DD], sq[DD], red[8];

    float x = g_slots[bs * DD + d];
    float a = x, c = x * x;
#pragma unroll
    for (int o = 16; o > 0; o >>= 1) {
        a += __shfl_xor_sync(~0u, a, o);
        c += __shfl_xor_sync(~0u, c, o);
    }
    if (ln == 0) { red[w] = a; red[4 + w] = c; }
    __syncthreads();
    float mean = (red[0] + red[1] + red[2] + red[3]) * (1.f / DD);
    float msq = (red[4] + red[5] + red[6] + red[7]) * (1.f / DD);
    float rstd = rsqrtf(msq - mean * mean + 1e-5f);
    lnq[d] = fmaf((x - mean) * rstd, lg[d], lb[d]);
    __syncthreads();

    float q = bq[d];
#pragma unroll 8
    for (int e = 0; e < DD; e++) q = fmaf(lnq[e], g_WqT[e * DD + d], q);
    sq[d] = q;
    __syncthreads();
    float qt = 0.f;
#pragma unroll 8
    for (int e = 0; e < DD; e++) qt = fmaf(sq[e], Wk[e * DD + d], qt);

    float wqv = qt * ling[d];
    float c1v = qt * linb[d];
    g_wq[bs * DD + d] = wqv;
    float aa = wqv, cc = c1v;
#pragma unroll
    for (int o = 16; o > 0; o >>= 1) {
        aa += __shfl_xor_sync(~0u, aa, o);
        cc += __shfl_xor_sync(~0u, cc, o);
    }
    __syncthreads();
    if (ln == 0) { red[w] = aa; red[4 + w] = cc; }
    __syncthreads();
    if (d == 0) {
        g_ws[bs] = red[0] + red[1] + red[2] + red[3];
        g_c1[bs] = red[4] + red[5] + red[6] + red[7];
    }
}

// ---------------- flash: 2 warps share the tile, s-split 4/3 -------------
__global__ void __launch_bounds__(64)
k_flash(const float* __restrict__ emb) {
    __shared__ float4 xt[32][33];       // 32 rows x 128 floats, padded
    __shared__ float4 wqs[SS][32];      // wq vectors
    __shared__ float ps[32][8];         // per-row probs*rstd
    const int t = threadIdx.x;
    const int lane = t & 31, wid = t >> 5;
    const int b = blockIdx.y, wk = blockIdx.x;

    for (int idx = t; idx < SS * 32; idx += 64)
        ((float4*)wqs)[idx] = ((const float4*)g_wq)[b * SS * 32 + idx];

    const int s_lo = wid * 4;           // warp0: s 0..3, warp1: s 4..6
    const int ns = 4 - wid;
    float ws[4], c1[4];
#pragma unroll
    for (int si = 0; si < 4; si++) {
        int s = s_lo + si;
        ws[si] = (si < ns) ? g_ws[b * SS + s] : 0.f;
        c1[si] = (si < ns) ? g_c1[b * SS + s] : 0.f;
    }

    float m[4], lsum[4], amsum[4];
    float4 acc[4];
#pragma unroll
    for (int si = 0; si < 4; si++) {
        m[si] = -INFINITY; lsum[si] = 0.f; amsum[si] = 0.f;
        acc[si] = make_float4(0.f, 0.f, 0.f, 0.f);
    }
    const float4* gbase = (const float4*)emb + (long long)(b * NN + wk * RPW) * 32;
    const float2* mvb = (const float2*)g_mv + (b * NN + wk * RPW);
    __syncthreads();

    for (int t2 = 0; t2 < RPW / 32; t2++) {
        // stage 32 rows cooperatively (each warp 16 rows)
#pragma unroll 4
        for (int k = 0; k < 16; k++) {
            int row = wid * 16 + k;
            xt[row][lane] = gbase[(t2 * 32 + row) * 32 + lane];
        }
        float2 mv = mvb[t2 * 32 + lane];
        __syncthreads();

        // logits for own row (row = lane), own s-subset
        float z[4] = {0.f, 0.f, 0.f, 0.f};
#pragma unroll 4
        for (int e = 0; e < 32; e++) {
            float4 xv = xt[lane][e];
#pragma unroll
            for (int si = 0; si < 4; si++) {
                if (si < ns) {
                    float4 wv = wqs[s_lo + si][e];
                    z[si] = fmaf(xv.x, wv.x, fmaf(xv.y, wv.y,
                            fmaf(xv.z, wv.z, fmaf(xv.w, wv.w, z[si]))));
                }
            }
        }
#pragma unroll
        for (int si = 0; si < 4; si++)
            z[si] = fmaf(mv.y, fmaf(-mv.x, ws[si], z[si]), c1[si]);

        // per-s warp max + rescale (warp-uniform branch)
#pragma unroll
        for (int si = 0; si < 4; si++) {
            if (si < ns) {
                float zm = z[si];
#pragma unroll
                for (int o = 16; o > 0; o >>= 1)
                    zm = fmaxf(zm, __shfl_xor_sync(~0u, zm, o));
                if (zm > m[si]) {
                    float sc = __expf(m[si] - zm);
                    m[si] = zm;
                    lsum[si] *= sc;
                    amsum[si] *= sc;
                    acc[si].x *= sc; acc[si].y *= sc; acc[si].z *= sc; acc[si].w *= sc;
                }
            }
        }
        float pr[4];
#pragma unroll
        for (int si = 0; si < 4; si++) {
            float pv = __expf(z[si] - m[si]);
            if (si < ns) lsum[si] += pv;
            pr[si] = pv * mv.y;
            if (si < ns) amsum[si] = fmaf(pr[si], mv.x, amsum[si]);
        }
        if (wid == 0)
            *(float4*)&ps[lane][0] = make_float4(pr[0], pr[1], pr[2], pr[3]);
        else
            *(float4*)&ps[lane][4] = make_float4(pr[0], pr[1], pr[2], 0.f);
        __syncthreads();

        // accumulate own s-subset over all 32 rows
#pragma unroll 4
        for (int r = 0; r < 32; r++) {
            float4 xv = xt[r][lane];
            float4 p = (wid == 0) ? *(const float4*)&ps[r][0]
                                  : *(const float4*)&ps[r][4];
            float prv[4] = {p.x, p.y, p.z, p.w};
#pragma unroll
            for (int si = 0; si < 4; si++) {
                if (si < ns) {
                    acc[si].x = fmaf(prv[si], xv.x, acc[si].x);
                    acc[si].y = fmaf(prv[si], xv.y, acc[si].y);
                    acc[si].z = fmaf(prv[si], xv.z, acc[si].z);
                    acc[si].w = fmaf(prv[si], xv.w, acc[si].w);
                }
            }
        }
        __syncthreads();
    }

#pragma unroll
    for (int si = 0; si < 4; si++) {
        float a = lsum[si], c = amsum[si];
#pragma unroll
        for (int o = 16; o > 0; o >>= 1) {
            a += __shfl_xor_sync(~0u, a, o);
            c += __shfl_xor_sync(~0u, c, o);
        }
        lsum[si] = a; amsum[si] = c;
    }
    const int pidx = b * NW + wk;
#pragma unroll
    for (int si = 0; si < 4; si++)
        if (si < ns)
            ((float4*)g_pax)[(pidx * SS + s_lo + si) * 32 + lane] = acc[si];
    if (lane == 0) {
#pragma unroll
        for (int si = 0; si < 4; si++) {
            if (si < ns) {
                g_pm[pidx * SS + s_lo + si] = m[si];
                g_pl[pidx * SS + s_lo + si] = lsum[si];
                g_pam[pidx * SS + s_lo + si] = amsum[si];
            }
        }
    }
}

// ---------------- k_up helpers ----------------
__device__ __forceinline__ float4 add4(float4 a, float4 b) {
    return make_float4(a.x + b.x, a.y + b.y, a.z + b.z, a.w + b.w);
}

// one e-sliced matmul pass: part[es][s][dg] = Σ_{e in slice} in[s][e] * W4[e*rs4+off+dg]
template<int NE>
__device__ __forceinline__ void mm_pass(const float4* __restrict__ W4, int rs4, int off,
                                        const float* __restrict__ in, int instride,
                                        float* __restrict__ partf, int dg, int es) {
    float4 a[SS];
#pragma unroll
    for (int s = 0; s < SS; s++) a[s] = make_float4(0.f, 0.f, 0.f, 0.f);
#pragma unroll 4
    for (int i = 0; i < NE; i++) {
        int e = es * NE + i;
        float4 wv = W4[e * rs4 + off + dg];
#pragma unroll
        for (int s = 0; s < SS; s++) {
            float v = in[s * instride + e];
            a[s].x = fmaf(v, wv.x, a[s].x);
            a[s].y = fmaf(v, wv.y, a[s].y);
            a[s].z = fmaf(v, wv.z, a[s].z);
            a[s].w = fmaf(v, wv.w, a[s].w);
        }
    }
    float4* p4 = (float4*)partf;
#pragma unroll
    for (int s = 0; s < SS; s++) p4[(es * SS + s) * 32 + dg] = a[s];
}

__device__ __forceinline__ float4 red8(const float* __restrict__ partf, int s, int lane) {
    const float4* p4 = (const float4*)partf;
    float4 r = p4[(0 * SS + s) * 32 + lane];
#pragma unroll
    for (int es = 1; es < 8; es++) {
        float4 q = p4[(es * SS + s) * 32 + lane];
        r.x += q.x; r.y += q.y; r.z += q.z; r.w += q.w;
    }
    return r;
}

// ---------------- combine + GRU + FF + next-q: one block per batch -------
__global__ void __launch_bounds__(256)
k_up(const float* __restrict__ bvv,
     const float* __restrict__ bih, const float* __restrict__ bhh,
     const float* __restrict__ b1, const float* __restrict__ b2,
     const float* __restrict__ lfg, const float* __restrict__ lfb,
     const float* __restrict__ bq, const float* __restrict__ Wk,
     const float* __restrict__ lsg, const float* __restrict__ lsb,
     const float* __restrict__ ling, const float* __restrict__ linb,
     float* __restrict__ out, int last) {
    const int b = blockIdx.x;
    const int t = threadIdx.x;
    const int lane = t & 31, w = t >> 5;
    const int dg = lane, es = w;       // matmul-pass indexing (8 slices x 32 dgroups)
    const int s = w;                   // output phase: warp w owns slot s (w<7)
    const bool act = (t < 224);

    __shared__ __align__(16) float sm[10768];
    float* part = sm;                  // [8][7][32] float4 partials (7168 f)
    float* swm  = sm;                  // alias: merge weights sw[s][sp] (448 f, pre-B only)
    float* suv  = sm + 7168;           // su -> lnv -> lnq (896 f)
    float* sxv  = sm + 8064;           // updates x -> q (896 f)
    float* shf  = sm + 8960;           // shh (896) then sf[7][256] (1792 f)
    float* sLp  = sm + 10752;          // L per s
    float* sAMp = sm + 10759;          // AM per s

    // ---- A: merge flash partials (warp w handles slot s=w) ----
    if (w < 7) {
        float pm0 = g_pm[(b * NW + lane) * SS + s];
        float pm1 = g_pm[(b * NW + 32 + lane) * SS + s];
        float mx = fmaxf(pm0, pm1);
#pragma unroll
        for (int o = 16; o > 0; o >>= 1) mx = fmaxf(mx, __shfl_xor_sync(~0u, mx, o));
        float w0 = __expf(pm0 - mx), w1 = __expf(pm1 - mx);
        swm[s * 64 + lane] = w0;
        swm[s * 64 + 32 + lane] = w1;
        float pl0 = g_pl[(b * NW + lane) * SS + s], pl1 = g_pl[(b * NW + 32 + lane) * SS + s];
        float pa0 = g_pam[(b * NW + lane) * SS + s], pa1 = g_pam[(b * NW + 32 + lane) * SS + s];
        float lw = fmaf(pl0, w0, pl1 * w1);
        float aw = fmaf(pa0, w0, pa1 * w1);
#pragma unroll
        for (int o = 16; o > 0; o >>= 1) {
            lw += __shfl_xor_sync(~0u, lw, o);
            aw += __shfl_xor_sync(~0u, aw, o);
        }
        if (lane == 0) { sLp[s] = lw; sAMp[s] = aw; }
    }
    __syncthreads();

    // ---- AX: merged numerator -> u ; load h ----
    float4 hv = make_float4(0.f, 0.f, 0.f, 0.f);
    if (act) {
        float4 a0 = make_float4(0.f, 0.f, 0.f, 0.f);
        float4 a1 = make_float4(0.f, 0.f, 0.f, 0.f);
        const float4* pax = (const float4*)g_pax + ((long long)(b * NW) * SS + s) * 32 + lane;
#pragma unroll 4
        for (int sp = 0; sp < NW; sp += 2) {
            float w0 = swm[s * 64 + sp], w1 = swm[s * 64 + sp + 1];
            float4 p0 = pax[sp * (SS * 32)];
            float4 p1 = pax[(sp + 1) * (SS * 32)];
            a0.x = fmaf(p0.x, w0, a0.x); a0.y = fmaf(p0.y, w0, a0.y);
            a0.z = fmaf(p0.z, w0, a0.z); a0.w = fmaf(p0.w, w0, a0.w);
            a1.x = fmaf(p1.x, w1, a1.x); a1.y = fmaf(p1.y, w1, a1.y);
            a1.z = fmaf(p1.z, w1, a1.z); a1.w = fmaf(p1.w, w1, a1.w);
        }
        float4 ax = add4(a0, a1);
        float L = sLp[s], AM = sAMp[s];
        float invL = 1.f / L;
        const float invC = 1.f / (1.f + (float)NN * EPSV);
        float4 lg4 = ((const float4*)ling)[lane];
        float4 lb4 = ((const float4*)linb)[lane];
        float4 es4 = ((const float4*)g_es)[b * 32 + lane];
        float4 su4;
        su4.x = (lg4.x * (ax.x - AM) * invL + lb4.x + EPSV * es4.x) * invC;
        su4.y = (lg4.y * (ax.y - AM) * invL + lb4.y + EPSV * es4.y) * invC;
        su4.z = (lg4.z * (ax.z - AM) * invL + lb4.z + EPSV * es4.z) * invC;
        su4.w = (lg4.w * (ax.w - AM) * invL + lb4.w + EPSV * es4.w) * invC;
        *(float4*)&suv[s * DD + lane * 4] = su4;
        hv = ((const float4*)g_slots)[(b * SS + s) * 32 + lane];
        *(float4*)&shf[s * DD + lane * 4] = hv;
    }
    __syncthreads();

    // ---- B: updates = u @ Wv^T + bv ----
    mm_pass<16>((const float4*)g_WvT, 32, 0, suv, DD, part, dg, es);
    __syncthreads();
    if (act) {
        float4 x4 = add4(red8(part, s, lane), ((const float4*)bvv)[lane]);
        *(float4*)&sxv[s * DD + lane * 4] = x4;
    }
    __syncthreads();

    // ---- C: GRU, 6 e-sliced passes (gates in registers) ----
    float4 gir, giz, gin, ghr, ghz, ghn;
    mm_pass<16>((const float4*)g_WihT, 96, 0, sxv, DD, part, dg, es);
    __syncthreads();
    if (act) gir = add4(red8(part, s, lane), ((const float4*)bih)[lane]);
    __syncthreads();
    mm_pass<16>((const float4*)g_WihT, 96, 32, sxv, DD, part, dg, es);
    __syncthreads();
    if (act) giz = add4(red8(part, s, lane), ((const float4*)bih)[32 + lane]);
    __syncthreads();
    mm_pass<16>((const float4*)g_WihT, 96, 64, sxv, DD, part, dg, es);
    __syncthreads();
    if (act) gin = add4(red8(part, s, lane), ((const float4*)bih)[64 + lane]);
    __syncthreads();
    mm_pass<16>((const float4*)g_WhhT, 96, 0, shf, DD, part, dg, es);
    __syncthreads();
    if (act) ghr = add4(red8(part, s, lane), ((const float4*)bhh)[lane]);
    __syncthreads();
    mm_pass<16>((const float4*)g_WhhT, 96, 32, shf, DD, part, dg, es);
    __syncthreads();
    if (act) ghz = add4(red8(part, s, lane), ((const float4*)bhh)[32 + lane]);
    __syncthreads();
    mm_pass<16>((const float4*)g_WhhT, 96, 64, shf, DD, part, dg, es);
    __syncthreads();
    float4 sv = make_float4(0.f, 0.f, 0.f, 0.f);
    if (act) {
        ghn = add4(red8(part, s, lane), ((const float4*)bhh)[64 + lane]);
        float rr, zz, nn;
        rr = 1.f / (1.f + expf(-(gir.x + ghr.x)));
        zz = 1.f / (1.f + expf(-(giz.x + ghz.x)));
        nn = tanhf(fmaf(rr, ghn.x, gin.x));
        sv.x = fmaf(zz, hv.x - nn, nn);
        rr = 1.f / (1.f + expf(-(gir.y + ghr.y)));
        zz = 1.f / (1.f + expf(-(giz.y + ghz.y)));
        nn = tanhf(fmaf(rr, ghn.y, gin.y));
        sv.y = fmaf(zz, hv.y - nn, nn);
        rr = 1.f / (1.f + expf(-(gir.z + ghr.z)));
        zz = 1.f / (1.f + expf(-(giz.z + ghz.z)));
        nn = tanhf(fmaf(rr, ghn.z, gin.z));
        sv.z = fmaf(zz, hv.z - nn, nn);
        rr = 1.f / (1.f + expf(-(gir.w + ghr.w)));
        zz = 1.f / (1.f + expf(-(giz.w + ghz.w)));
        nn = tanhf(fmaf(rr, ghn.w, gin.w));
        sv.w = fmaf(zz, hv.w - nn, nn);
    }

    // ---- D: LN_ff (warp-per-slot reduce; warp 7 computes garbage, unused) ----
    {
        float a = sv.x + sv.y + sv.z + sv.w;
        float c = fmaf(sv.x, sv.x, fmaf(sv.y, sv.y, fmaf(sv.z, sv.z, sv.w * sv.w)));
#pragma unroll
        for (int o = 16; o > 0; o >>= 1) {
            a += __shfl_xor_sync(~0u, a, o);
            c += __shfl_xor_sync(~0u, c, o);
        }
        float mean = a * (1.f / DD);
        float rstd = rsqrtf(c * (1.f / DD) - mean * mean + 1e-5f);
        if (act) {
            float4 g4 = ((const float4*)lfg)[lane];
            float4 bb4 = ((const float4*)lfb)[lane];
            float4 lv;
            lv.x = fmaf((sv.x - mean) * rstd, g4.x, bb4.x);
            lv.y = fmaf((sv.y - mean) * rstd, g4.y, bb4.y);
            lv.z = fmaf((sv.z - mean) * rstd, g4.z, bb4.z);
            lv.w = fmaf((sv.w - mean) * rstd, g4.w, bb4.w);
            *(float4*)&suv[s * DD + lane * 4] = lv;   // lnv (su dead)
        }
    }
    __syncthreads();

    // ---- E: FF1 (relu), two output halves ----
    mm_pass<16>((const float4*)g_W1T, 64, 0, suv, DD, part, dg, es);
    __syncthreads();
    if (act) {
        float4 f = add4(red8(part, s, lane), ((const float4*)b1)[lane]);
        f.x = fmaxf(f.x, 0.f); f.y = fmaxf(f.y, 0.f);
        f.z = fmaxf(f.z, 0.f); f.w = fmaxf(f.w, 0.f);
        *(float4*)&shf[s * HH + lane * 4] = f;        // sf (shh dead)
    }
    __syncthreads();
    mm_pass<16>((const float4*)g_W1T, 64, 32, suv, DD, part, dg, es);
    __syncthreads();
    if (act) {
        float4 f = add4(red8(part, s, lane), ((const float4*)b1)[32 + lane]);
        f.x = fmaxf(f.x, 0.f); f.y = fmaxf(f.y, 0.f);
        f.z = fmaxf(f.z, 0.f); f.w = fmaxf(f.w, 0.f);
        *(float4*)&shf[s * HH + DD + lane * 4] = f;
    }
    __syncthreads();

    // ---- F: FF2 + residual ----
    mm_pass<32>((const float4*)g_W2T, 32, 0, shf, HH, part, dg, es);
    __syncthreads();
    float4 res = make_float4(0.f, 0.f, 0.f, 0.f);
    if (act) {
        float4 o2 = add4(red8(part, s, lane), ((const float4*)b2)[lane]);
        res.x = sv.x + o2.x; res.y = sv.y + o2.y;
        res.z = sv.z + o2.z; res.w = sv.w + o2.w;
        ((float4*)g_slots)[(b * SS + s) * 32 + lane] = res;
        if (last) ((float4*)out)[(b * SS + s) * 32 + lane] = res;
    }

    if (!last) {
        // ---- G1: LN_s (warp-per-slot reduce) ----
        {
            float a = res.x + res.y + res.z + res.w;
            float c = fmaf(res.x, res.x, fmaf(res.y, res.y, fmaf(res.z, res.z, res.w * res.w)));
#pragma unroll
            for (int o = 16; o > 0; o >>= 1) {
                a += __shfl_xor_sync(~0u, a, o);
                c += __shfl_xor_sync(~0u, c, o);
            }
            float mean = a * (1.f / DD);
            float rstd = rsqrtf(c * (1.f / DD) - mean * mean + 1e-5f);
            if (act) {
                float4 g4 = ((const float4*)lsg)[lane];
                float4 bb4 = ((const float4*)lsb)[lane];
                float4 lq;
                lq.x = fmaf((res.x - mean) * rstd, g4.x, bb4.x);
                lq.y = fmaf((res.y - mean) * rstd, g4.y, bb4.y);
                lq.z = fmaf((res.z - mean) * rstd, g4.z, bb4.z);
                lq.w = fmaf((res.w - mean) * rstd, g4.w, bb4.w);
                *(float4*)&suv[s * DD + lane * 4] = lq;    // lnq
            }
        }
        __syncthreads();
        // ---- G2: q = lnq @ WqT + bq ----
        mm_pass<16>((const float4*)g_WqT, 32, 0, suv, DD, part, dg, es);
        __syncthreads();
        if (act) {
            float4 q4 = add4(red8(part, s, lane), ((const float4*)bq)[lane]);
            *(float4*)&sxv[s * DD + lane * 4] = q4;
        }
        __syncthreads();
        // ---- G3: qt = q @ Wk  (Wk already e-major) ----
        mm_pass<16>((const float4*)Wk, 32, 0, sxv, DD, part, dg, es);
        __syncthreads();
        if (act) {
            float4 qt = red8(part, s, lane);
            float4 lg4 = ((const float4*)ling)[lane];
            float4 lb4 = ((const float4*)linb)[lane];
            float4 wq4;
            wq4.x = qt.x * lg4.x; wq4.y = qt.y * lg4.y;
            wq4.z = qt.z * lg4.z; wq4.w = qt.w * lg4.w;
            ((float4*)g_wq)[(b * SS + s) * 32 + lane] = wq4;
            float wss = wq4.x + wq4.y + wq4.z + wq4.w;
            float c1s = fmaf(qt.x, lb4.x, fmaf(qt.y, lb4.y,
                        fmaf(qt.z, lb4.z, qt.w * lb4.w)));
#pragma unroll
            for (int o = 16; o > 0; o >>= 1) {
                wss += __shfl_xor_sync(~0u, wss, o);
                c1s += __shfl_xor_sync(~0u, c1s, o);
            }
            if (lane == 0) { g_ws[b * SS + s] = wss; g_c1[b * SS + s] = c1s; }
        }
    }
}

// ---------------- launch ----------------
extern "C" void kernel_launch(void* const* d_in, const int* in_sizes, int n_in,
                              void* d_out, int out_size) {
    (void)in_sizes; (void)n_in; (void)out_size;
    const float* emb   = (const float*)d_in[0];
    const float* noise = (const float*)d_in[1];
    const float* mu    = (const float*)d_in[2];
    const float* sg    = (const float*)d_in[3];
    const float* Wk    = (const float*)d_in[4];
    /* bk = d_in[5] unused: constant per-(b,s) logit shift cancels in softmax */
    const float* Wq    = (const float*)d_in[6];
    const float* bq    = (const float*)d_in[7];
    const float* Wv    = (const float*)d_in[8];
    const float* bvv   = (const float*)d_in[9];
    const float* Wih   = (const float*)d_in[10];
    const float* Whh   = (const float*)d_in[11];
    const float* bih   = (const float*)d_in[12];
    const float* bhh   = (const float*)d_in[13];
    const float* W1    = (const float*)d_in[14];
    const float* b1    = (const float*)d_in[15];
    const float* W2    = (const float*)d_in[16];
    const float* b2    = (const float*)d_in[17];
    const float* lin_g = (const float*)d_in[18];
    const float* lin_b = (const float*)d_in[19];
    const float* ls_g  = (const float*)d_in[20];
    const float* ls_b  = (const float*)d_in[21];
    const float* lf_g  = (const float*)d_in[22];
    const float* lf_b  = (const float*)d_in[23];
    float* out = (float*)d_out;

    k_trinit<<<416, 256>>>(Wq, Wv, Wih, Whh, W1, W2, noise, mu, sg);   // #1
    k_prep<<<dim3(8, BB), 256>>>(emb);                                  // #2
    k_q0<<<BB * SS, DD>>>(bq, Wk, ls_g, ls_b, lin_g, lin_b);            // #3
    for (int it = 0; it < 3; it++) {
        k_flash<<<dim3(NW, BB), 64>>>(emb);                             // #4 on it==0
        if (it == 0) k_es<<<BB, DD>>>(lin_g, lin_b);                    // #5
        k_up<<<BB, 256>>>(bvv, bih, bhh, b1, b2, lf_g, lf_b,
                          bq, Wk, ls_g, ls_b, lin_g, lin_b, out, it == 2);
    }
}